// round 1
// baseline (speedup 1.0000x reference)
#include <cuda_runtime.h>
#include <math.h>

#define S_ 196
#define B_ 64
#define E_ 1024
#define D_ 1800
#define W_ 512
#define V_ 32000
#define WE_ (W_ + E_)     // 1536
#define DE_ (D_ + E_)     // 2824
#define DWE_ (D_ + W_ + E_) // 3336

// ---------------------------------------------------------------------------
// Scratch (device globals: the only legal scratch under the alloc guards)
// ---------------------------------------------------------------------------
struct Scratch {
    float havg[B_ * E_];
    float t1[B_ * D_];
    float t2[B_ * D_];
    float h0[B_ * D_];
    float c0[B_ * D_];
    float qpart[B_ * D_];     // h0 @ Wa1[:, :D].T + ba1
    float scores[S_ * B_];
    float beta[B_];
    float ctx[B_ * E_];
    float x[B_ * WE_];
    float gates[B_ * 4 * D_];
    float z[B_ * DWE_];
    int   amax[B_];
};
__device__ Scratch g_s;

// ---------------------------------------------------------------------------
// Generic GEMM: C[64, N] = act(A[64, K] @ Wt[N, K]^T + bias)   (ldc = N)
// Wt has row stride ldw (>= K) so weight slices (Wa1 cols) work.
// One block computes a 64(M) x 64(N) tile. 256 threads, 4x4 microtile.
// ---------------------------------------------------------------------------
template <bool RELU, bool ACCUM>
__global__ __launch_bounds__(256) void gemm64(
    const float* __restrict__ A, int K,
    const float* __restrict__ Wt, int ldw, int N,
    const float* __restrict__ bias,
    float* __restrict__ C)
{
    __shared__ __align__(16) float As[16][64];
    __shared__ __align__(16) float Ws[16][64];

    const int tid = threadIdx.x;
    const int tx = tid & 15;        // n-direction (4 cols each)
    const int ty = tid >> 4;        // m-direction (4 rows each)
    const int lr = tid >> 2;        // load row 0..63
    const int lk = (tid & 3) * 4;   // k offset within 16-wide tile
    const int nb = blockIdx.x * 64;

    const float* Arow = A + (size_t)lr * K;
    const float* Wrow = (nb + lr < N) ? (Wt + (size_t)(nb + lr) * ldw) : nullptr;

    float acc[4][4] = {};

    for (int k0 = 0; k0 < K; k0 += 16) {
        __syncthreads();
        // A tile (M=64 always full)
        float4 av;
        if (k0 + 16 <= K) {
            av = *(const float4*)(Arow + k0 + lk);
        } else {
            float t0 = (k0 + lk + 0 < K) ? Arow[k0 + lk + 0] : 0.f;
            float t1v = (k0 + lk + 1 < K) ? Arow[k0 + lk + 1] : 0.f;
            float t2v = (k0 + lk + 2 < K) ? Arow[k0 + lk + 2] : 0.f;
            float t3 = (k0 + lk + 3 < K) ? Arow[k0 + lk + 3] : 0.f;
            av = make_float4(t0, t1v, t2v, t3);
        }
        As[lk + 0][lr] = av.x; As[lk + 1][lr] = av.y;
        As[lk + 2][lr] = av.z; As[lk + 3][lr] = av.w;
        // W tile (guard row and K tail)
        float4 wv = make_float4(0.f, 0.f, 0.f, 0.f);
        if (Wrow) {
            if (k0 + 16 <= K) {
                wv = *(const float4*)(Wrow + k0 + lk);
            } else {
                wv.x = (k0 + lk + 0 < K) ? Wrow[k0 + lk + 0] : 0.f;
                wv.y = (k0 + lk + 1 < K) ? Wrow[k0 + lk + 1] : 0.f;
                wv.z = (k0 + lk + 2 < K) ? Wrow[k0 + lk + 2] : 0.f;
                wv.w = (k0 + lk + 3 < K) ? Wrow[k0 + lk + 3] : 0.f;
            }
        }
        Ws[lk + 0][lr] = wv.x; Ws[lk + 1][lr] = wv.y;
        Ws[lk + 2][lr] = wv.z; Ws[lk + 3][lr] = wv.w;
        __syncthreads();

        #pragma unroll
        for (int kk = 0; kk < 16; kk++) {
            float4 a4 = *(const float4*)(&As[kk][ty * 4]);
            float4 w4 = *(const float4*)(&Ws[kk][tx * 4]);
            float ar[4] = {a4.x, a4.y, a4.z, a4.w};
            float wr[4] = {w4.x, w4.y, w4.z, w4.w};
            #pragma unroll
            for (int i = 0; i < 4; i++)
                #pragma unroll
                for (int j = 0; j < 4; j++)
                    acc[i][j] = fmaf(ar[i], wr[j], acc[i][j]);
        }
    }

    #pragma unroll
    for (int j = 0; j < 4; j++) {
        int n = nb + tx * 4 + j;
        if (n < N) {
            float bv = bias[n];
            #pragma unroll
            for (int i = 0; i < 4; i++) {
                float v = acc[i][j] + bv;
                if (RELU) v = fmaxf(v, 0.f);
                float* c = C + (size_t)(ty * 4 + i) * N + n;
                if (ACCUM) *c += v; else *c = v;
            }
        }
    }
}

// ---------------------------------------------------------------------------
// Fused attention scores: one block per seq position s (rows = all 64 batches).
// score[s,b] = ba2 + sum_n Wa2[n] * relu( qpart[b,n] + h[s,b,:] . Wa1[n, D:] )
// GEMM tile loop over n with in-register relu/Wa2 reduction -> never
// materializes the 12544x1800 intermediate (90 MB saved each way).
// ---------------------------------------------------------------------------
__global__ __launch_bounds__(256) void scores_kernel(
    const float* __restrict__ h,      // [S*B, E] contiguous
    const float* __restrict__ Wa1h,   // Wa1 + D_, row stride DE_
    const float* __restrict__ qpart,  // [B, D] (includes ba1)
    const float* __restrict__ Wa2,    // [D]
    const float* __restrict__ ba2,    // [1]
    float* __restrict__ scores)       // [S*B]
{
    __shared__ __align__(16) float As[16][64];
    __shared__ __align__(16) float Ws[16][64];
    __shared__ float red[64][17];

    const int tid = threadIdx.x;
    const int tx = tid & 15;
    const int ty = tid >> 4;
    const int lr = tid >> 2;
    const int lk = (tid & 3) * 4;
    const int s = blockIdx.x;

    const float* Arow = h + ((size_t)s * B_ + lr) * E_;
    float sacc[4] = {0.f, 0.f, 0.f, 0.f};

    for (int nb = 0; nb < D_; nb += 64) {
        float acc[4][4] = {};
        const float* Wrow = (nb + lr < D_) ? (Wa1h + (size_t)(nb + lr) * DE_) : nullptr;

        for (int k0 = 0; k0 < E_; k0 += 16) {   // E_ % 16 == 0
            __syncthreads();
            float4 av = *(const float4*)(Arow + k0 + lk);
            As[lk + 0][lr] = av.x; As[lk + 1][lr] = av.y;
            As[lk + 2][lr] = av.z; As[lk + 3][lr] = av.w;
            float4 wv = make_float4(0.f, 0.f, 0.f, 0.f);
            if (Wrow) wv = *(const float4*)(Wrow + k0 + lk);
            Ws[lk + 0][lr] = wv.x; Ws[lk + 1][lr] = wv.y;
            Ws[lk + 2][lr] = wv.z; Ws[lk + 3][lr] = wv.w;
            __syncthreads();

            #pragma unroll
            for (int kk = 0; kk < 16; kk++) {
                float4 a4 = *(const float4*)(&As[kk][ty * 4]);
                float4 w4 = *(const float4*)(&Ws[kk][tx * 4]);
                float ar[4] = {a4.x, a4.y, a4.z, a4.w};
                float wr[4] = {w4.x, w4.y, w4.z, w4.w};
                #pragma unroll
                for (int i = 0; i < 4; i++)
                    #pragma unroll
                    for (int j = 0; j < 4; j++)
                        acc[i][j] = fmaf(ar[i], wr[j], acc[i][j]);
            }
        }
        // tile epilogue: relu + Wa2-weighted reduce over n
        #pragma unroll
        for (int j = 0; j < 4; j++) {
            int n = nb + tx * 4 + j;
            if (n < D_) {
                float w2 = Wa2[n];
                #pragma unroll
                for (int i = 0; i < 4; i++) {
                    float v = acc[i][j] + qpart[(size_t)(ty * 4 + i) * D_ + n];
                    sacc[i] = fmaf(fmaxf(v, 0.f), w2, sacc[i]);
                }
            }
        }
    }

    #pragma unroll
    for (int i = 0; i < 4; i++) red[ty * 4 + i][tx] = sacc[i];
    __syncthreads();
    if (tid < 64) {
        float t = 0.f;
        #pragma unroll
        for (int j = 0; j < 16; j++) t += red[tid][j];
        scores[(size_t)s * B_ + tid] = t + ba2[0];
    }
}

// ---------------------------------------------------------------------------
// Small kernels
// ---------------------------------------------------------------------------
__global__ void havg_kernel(const float* __restrict__ h, float* __restrict__ havg)
{
    int b = blockIdx.x;
    int e = blockIdx.y * 256 + threadIdx.x;
    float s = 0.f;
    for (int si = 0; si < S_; si++)
        s += h[((size_t)si * B_ + b) * E_ + e];
    havg[(size_t)b * E_ + e] = s * (1.f / (float)S_);
}

__global__ __launch_bounds__(256) void softmax_beta_kernel(
    const float* __restrict__ scores, const float* __restrict__ h0,
    const float* __restrict__ Wb, const float* __restrict__ bb,
    float* __restrict__ aw_out, float* __restrict__ beta)
{
    int b = blockIdx.x, tid = threadIdx.x;
    __shared__ float sm[256];

    // beta[b] = sigmoid(h0[b] . Wb + bb)
    float p = 0.f;
    for (int d = tid; d < D_; d += 256) p = fmaf(h0[(size_t)b * D_ + d], Wb[d], p);
    sm[tid] = p; __syncthreads();
    for (int o = 128; o > 0; o >>= 1) { if (tid < o) sm[tid] += sm[tid + o]; __syncthreads(); }
    if (tid == 0) beta[b] = 1.f / (1.f + expf(-(sm[0] + bb[0])));
    __syncthreads();

    // softmax over S (196 values)
    float v = (tid < S_) ? scores[(size_t)tid * B_ + b] : -3.4e38f;
    sm[tid] = v; __syncthreads();
    for (int o = 128; o > 0; o >>= 1) { if (tid < o) sm[tid] = fmaxf(sm[tid], sm[tid + o]); __syncthreads(); }
    float mx = sm[0]; __syncthreads();
    float e = (tid < S_) ? expf(v - mx) : 0.f;
    sm[tid] = e; __syncthreads();
    for (int o = 128; o > 0; o >>= 1) { if (tid < o) sm[tid] += sm[tid + o]; __syncthreads(); }
    float inv = 1.f / sm[0];
    if (tid < S_) aw_out[(size_t)tid * B_ + b] = e * inv;
}

__global__ void ctx_kernel(const float* __restrict__ h, const float* __restrict__ aw,
                           const float* __restrict__ beta, float* __restrict__ ctx)
{
    int b = blockIdx.x;
    int e = blockIdx.y * 256 + threadIdx.x;
    float s = 0.f;
    for (int si = 0; si < S_; si++)
        s = fmaf(aw[(size_t)si * B_ + b], h[((size_t)si * B_ + b) * E_ + e], s);
    ctx[(size_t)b * E_ + e] = s * beta[b];
}

__global__ __launch_bounds__(256) void argmax_kernel(const float* __restrict__ y, int* __restrict__ amax)
{
    int b = blockIdx.x, tid = threadIdx.x;
    float bm = -3.4e38f; int bi = 0;
    for (int i = tid; i < V_; i += 256) {
        float v = y[(size_t)b * V_ + i];
        if (v > bm) { bm = v; bi = i; }
    }
    __shared__ float sv[256];
    __shared__ int si_[256];
    sv[tid] = bm; si_[tid] = bi; __syncthreads();
    for (int o = 128; o > 0; o >>= 1) {
        if (tid < o) {
            if (sv[tid + o] > sv[tid] || (sv[tid + o] == sv[tid] && si_[tid + o] < si_[tid])) {
                sv[tid] = sv[tid + o]; si_[tid] = si_[tid + o];
            }
        }
        __syncthreads();
    }
    if (tid == 0) amax[b] = si_[0];
}

__global__ void xbuild_kernel(const float* __restrict__ emb, const int* __restrict__ Etm1,
                              const float* __restrict__ ctx, float* __restrict__ x)
{
    int b = blockIdx.x;
    int i = blockIdx.y * 256 + threadIdx.x;   // grid.y = 6 -> i in [0,1536)
    if (i < W_) x[(size_t)b * WE_ + i] = emb[(size_t)Etm1[b] * W_ + i];
    else        x[(size_t)b * WE_ + i] = ctx[(size_t)b * E_ + (i - W_)];
}

__global__ void lstm_kernel(const float* __restrict__ gates, const float* __restrict__ c0,
                            float* __restrict__ out, float* __restrict__ z)
{
    int b = blockIdx.x;
    int d = blockIdx.y * 256 + threadIdx.x;
    if (d >= D_) return;
    const float* g = gates + (size_t)b * 4 * D_;
    float ig = 1.f / (1.f + expf(-g[d]));
    float fg = 1.f / (1.f + expf(-g[D_ + d]));
    float gg = tanhf(g[2 * D_ + d]);
    float og = 1.f / (1.f + expf(-g[3 * D_ + d]));
    float c = fmaf(fg, c0[(size_t)b * D_ + d], ig * gg);
    float ht = og * tanhf(c);
    out[(size_t)B_ * V_ + (size_t)b * D_ + d] = ht;                     // h_t
    out[(size_t)B_ * V_ + (size_t)B_ * D_ + (size_t)b * D_ + d] = c;    // c_t
    z[(size_t)b * DWE_ + d] = ht;
}

__global__ void zbuild_kernel(const float* __restrict__ emb, const int* __restrict__ amax,
                              const float* __restrict__ ctx, float* __restrict__ z)
{
    int b = blockIdx.x;
    int i = blockIdx.y * 256 + threadIdx.x;   // grid.y = 6 -> i in [0,1536)
    if (i < W_) z[(size_t)b * DWE_ + D_ + i] = emb[(size_t)amax[b] * W_ + i];
    else        z[(size_t)b * DWE_ + D_ + i] = ctx[(size_t)b * E_ + (i - W_)];
}

// ---------------------------------------------------------------------------
// Launch
// ---------------------------------------------------------------------------
extern "C" void kernel_launch(void* const* d_in, const int* in_sizes, int n_in,
                              void* d_out, int out_size)
{
    const int*   E_tm1 = (const int*)d_in[0];
    const float* y_tm1 = (const float*)d_in[1];
    const float* h     = (const float*)d_in[2];
    const float* emb   = (const float*)d_in[3];
    const float* W_ih  = (const float*)d_in[4];
    const float* b_ih  = (const float*)d_in[5];
    const float* W_hh  = (const float*)d_in[6];
    const float* b_hh  = (const float*)d_in[7];
    const float* W_out = (const float*)d_in[8];
    const float* b_out = (const float*)d_in[9];
    const float* Wh1 = (const float*)d_in[10]; const float* bh1 = (const float*)d_in[11];
    const float* Wh2 = (const float*)d_in[12]; const float* bh2 = (const float*)d_in[13];
    const float* Wc1 = (const float*)d_in[14]; const float* bc1 = (const float*)d_in[15];
    const float* Wc2 = (const float*)d_in[16]; const float* bc2 = (const float*)d_in[17];
    const float* Wa1 = (const float*)d_in[18]; const float* ba1 = (const float*)d_in[19];
    const float* Wa2 = (const float*)d_in[20]; const float* ba2 = (const float*)d_in[21];
    const float* Wb  = (const float*)d_in[22]; const float* bb  = (const float*)d_in[23];
    float* out = (float*)d_out;

    Scratch* s = nullptr;
    cudaGetSymbolAddress((void**)&s, g_s);

    const int GN_D  = (D_ + 63) / 64;        // 29
    const int GN_4D = (4 * D_ + 63) / 64;    // 113
    const int GN_V  = V_ / 64;               // 500

    // 1. encoder mean
    havg_kernel<<<dim3(B_, E_ / 256), 256>>>(h, s->havg);
    // 2. init-state MLPs
    gemm64<true,  false><<<GN_D, 256>>>(s->havg, E_, Wh1, E_, D_, bh1, s->t1);
    gemm64<true,  false><<<GN_D, 256>>>(s->havg, E_, Wc1, E_, D_, bc1, s->t2);
    gemm64<false, false><<<GN_D, 256>>>(s->t1, D_, Wh2, D_, D_, bh2, s->h0);
    gemm64<false, false><<<GN_D, 256>>>(s->t2, D_, Wc2, D_, D_, bc2, s->c0);
    // 3. attention: factored query part (K = D, Wa1 cols [0, D))
    gemm64<false, false><<<GN_D, 256>>>(s->h0, D_, Wa1, DE_, D_, ba1, s->qpart);
    // 4. fused scores GEMM (key part, Wa1 cols [D, D+E))
    scores_kernel<<<S_, 256>>>(h, Wa1 + D_, s->qpart, Wa2, ba2, s->scores);
    // 5. argmax of y_tm1 (independent)
    argmax_kernel<<<B_, 256>>>(y_tm1, s->amax);
    // 6. softmax over S + beta gate; aw written directly to output
    float* aw_out = out + (size_t)B_ * V_ + 2 * (size_t)B_ * D_;
    softmax_beta_kernel<<<B_, 256>>>(s->scores, s->h0, Wb, bb, aw_out, s->beta);
    // 7. context vector (scaled by beta)
    ctx_kernel<<<dim3(B_, E_ / 256), 256>>>(h, aw_out, s->beta, s->ctx);
    // 8. LSTM input + gates
    xbuild_kernel<<<dim3(B_, WE_ / 256), 256>>>(emb, E_tm1, s->ctx, s->x);
    gemm64<false, false><<<GN_4D, 256>>>(s->x,  WE_, W_ih, WE_, 4 * D_, b_ih, s->gates);
    gemm64<false, true ><<<GN_4D, 256>>>(s->h0, D_,  W_hh, D_,  4 * D_, b_hh, s->gates);
    // 9. LSTM pointwise -> h_t, c_t (into out) + z[:, :D]
    lstm_kernel<<<dim3(B_, (D_ + 255) / 256), 256>>>(s->gates, s->c0, out, s->z);
    // 10. z = [h_t, y_emb, ctx]
    zbuild_kernel<<<dim3(B_, WE_ / 256), 256>>>(emb, s->amax, s->ctx, s->z);
    // 11. logits -> out[0 : B*V]
    gemm64<false, false><<<GN_V, 256>>>(s->z, DWE_, W_out, DWE_, V_, b_out, out);
}

// round 2
// speedup vs baseline: 2.8329x; 2.8329x over previous
#include <cuda_runtime.h>
#include <math.h>
#include <stdint.h>

#define S_ 196
#define B_ 64
#define E_ 1024
#define D_ 1800
#define W_ 512
#define V_ 32000
#define WE_ (W_ + E_)       // 1536
#define DE_ (D_ + E_)       // 2824
#define DWE_ (D_ + W_ + E_) // 3336

// ---------------------------------------------------------------------------
// Scratch
// ---------------------------------------------------------------------------
struct Scratch {
    float havg[B_ * E_];
    float t1[B_ * D_];
    float t2[B_ * D_];
    float h0[B_ * D_];
    float c0[B_ * D_];
    float qpart[B_ * D_];
    float spart[3 * S_ * B_];
    float beta[B_];
    float ctx[B_ * E_];
    float x[B_ * WE_];
    float gates[B_ * 4 * D_];
    float z[B_ * DWE_];
    int   amax[B_];
};
__device__ Scratch g_s;

// ---------------------------------------------------------------------------
// tf32 helpers
// ---------------------------------------------------------------------------
__device__ __forceinline__ uint32_t f2tf32(float f) {
    uint32_t u;
    asm("cvt.rna.tf32.f32 %0, %1;" : "=r"(u) : "f"(f));
    return u;
}

__device__ __forceinline__ void mma_tf32(float (&c)[4], const uint32_t (&a)[4],
                                         const uint32_t b0, const uint32_t b1) {
    asm volatile(
        "mma.sync.aligned.m16n8k8.row.col.f32.tf32.tf32.f32 "
        "{%0,%1,%2,%3},{%4,%5,%6,%7},{%8,%9},{%0,%1,%2,%3};"
        : "+f"(c[0]), "+f"(c[1]), "+f"(c[2]), "+f"(c[3])
        : "r"(a[0]), "r"(a[1]), "r"(a[2]), "r"(a[3]), "r"(b0), "r"(b1));
}

// ---------------------------------------------------------------------------
// One K-segment of a 64 x BN GEMM tile, tf32 MMA, fp32 accumulate.
// A: [64, K] row-major (lda == K). W: [N, K] row-major, row stride ldw.
// As/Ws layout: [row][k] with row stride 36 (conflict-free mma loads).
// 1-deep register prefetch of the next gmem tile during compute.
// ---------------------------------------------------------------------------
template<int BN>
__device__ __forceinline__ void gemm_segment(
    const float* __restrict__ A, const float* __restrict__ W,
    const int K, const int ldw, const int N, const int nb,
    uint32_t As[64][36], uint32_t Ws[BN][36],
    float (&acc)[2][BN / 32][4])
{
    constexpr int NF  = BN / 32;   // n-frags per warp
    constexpr int WPT = BN / 8;    // W floats per thread (8 or 16)
    const int tid  = threadIdx.x;
    const int lane = tid & 31, wid = tid >> 5;
    const int warpM = wid >> 2, warpN = wid & 3;
    const int g = lane >> 2, t = lane & 3;
    const int am  = tid & 63, akg = (tid >> 6) * 8;
    const int wn  = (BN == 64) ? (tid & 63) : (tid & 127);
    const int wkg = (BN == 64) ? ((tid >> 6) * 8) : ((tid >> 7) * 16);
    const bool wvalid = (nb + wn) < N;
    const float* Abase = A + (size_t)am * K;
    const float* Wbase = W + (size_t)(nb + wn) * ldw;

    float ra[8];
    float rw[WPT];

    const int T = (K + 31) >> 5;

    auto loadA = [&](int ti) {
        const int k0 = ti * 32 + akg;
        if (k0 + 8 <= K) {
            float4 v0 = *(const float4*)(Abase + k0);
            float4 v1 = *(const float4*)(Abase + k0 + 4);
            ra[0] = v0.x; ra[1] = v0.y; ra[2] = v0.z; ra[3] = v0.w;
            ra[4] = v1.x; ra[5] = v1.y; ra[6] = v1.z; ra[7] = v1.w;
        } else {
            #pragma unroll
            for (int i = 0; i < 8; i++)
                ra[i] = (k0 + i < K) ? Abase[k0 + i] : 0.f;
        }
    };
    auto loadW = [&](int ti) {
        const int k0 = ti * 32 + wkg;
        if (wvalid && k0 + WPT <= K) {
            #pragma unroll
            for (int i = 0; i < WPT / 4; i++) {
                float4 v = *(const float4*)(Wbase + k0 + i * 4);
                rw[i * 4 + 0] = v.x; rw[i * 4 + 1] = v.y;
                rw[i * 4 + 2] = v.z; rw[i * 4 + 3] = v.w;
            }
        } else {
            #pragma unroll
            for (int i = 0; i < WPT; i++)
                rw[i] = (wvalid && (k0 + i) < K) ? Wbase[k0 + i] : 0.f;
        }
    };

    loadA(0);
    loadW(0);

    for (int ti = 0; ti < T; ti++) {
        __syncthreads();
        #pragma unroll
        for (int i = 0; i < 8; i++) As[am][akg + i] = f2tf32(ra[i]);
        #pragma unroll
        for (int i = 0; i < WPT; i++) Ws[wn][wkg + i] = f2tf32(rw[i]);
        __syncthreads();

        if (ti + 1 < T) { loadA(ti + 1); loadW(ti + 1); }

        #pragma unroll
        for (int ks = 0; ks < 4; ks++) {
            const int kb = ks * 8;
            uint32_t a[2][4];
            #pragma unroll
            for (int mf = 0; mf < 2; mf++) {
                const int r = warpM * 32 + mf * 16 + g;
                a[mf][0] = As[r][kb + t];
                a[mf][1] = As[r + 8][kb + t];
                a[mf][2] = As[r][kb + t + 4];
                a[mf][3] = As[r + 8][kb + t + 4];
            }
            #pragma unroll
            for (int nf = 0; nf < NF; nf++) {
                const int n = warpN * (BN / 4) + nf * 8 + g;
                const uint32_t b0 = Ws[n][kb + t];
                const uint32_t b1 = Ws[n][kb + t + 4];
                #pragma unroll
                for (int mf = 0; mf < 2; mf++)
                    mma_tf32(acc[mf][nf], a[mf], b0, b1);
            }
        }
    }
}

// ---------------------------------------------------------------------------
// Generic GEMM kernel: C[64, N] = act(A1 @ W1^T [+ A2 @ W2^T] + b1 [+ b2])
// blockIdx.y selects one of two jobs (for fused independent GEMMs).
// ---------------------------------------------------------------------------
struct Job {
    const float* A1; const float* W1; int K1; int ldw1;
    const float* A2; const float* W2; int K2; int ldw2;
    const float* b1; const float* b2;
    float* C; int N;
};
struct Job2 { Job j[2]; };

template<int BN, bool RELU>
__global__ __launch_bounds__(256) void mma_gemm_kernel(Job2 jobs)
{
    constexpr int NF = BN / 32;
    __shared__ uint32_t As[64][36];
    __shared__ uint32_t Ws[BN][36];

    const Job j = jobs.j[blockIdx.y];
    const int nb = blockIdx.x * BN;
    if (nb >= j.N) return;

    float acc[2][NF][4];
    #pragma unroll
    for (int mf = 0; mf < 2; mf++)
        #pragma unroll
        for (int nf = 0; nf < NF; nf++)
            #pragma unroll
            for (int i = 0; i < 4; i++) acc[mf][nf][i] = 0.f;

    gemm_segment<BN>(j.A1, j.W1, j.K1, j.ldw1, j.N, nb, As, Ws, acc);
    if (j.A2)
        gemm_segment<BN>(j.A2, j.W2, j.K2, j.ldw2, j.N, nb, As, Ws, acc);

    const int tid = threadIdx.x, lane = tid & 31, wid = tid >> 5;
    const int warpM = wid >> 2, warpN = wid & 3;
    const int g = lane >> 2, t = lane & 3;

    #pragma unroll
    for (int mf = 0; mf < 2; mf++) {
        const int row = warpM * 32 + mf * 16 + g;
        #pragma unroll
        for (int nf = 0; nf < NF; nf++) {
            const int col = nb + warpN * (BN / 4) + nf * 8 + 2 * t;
            if (col < j.N) {
                float b0 = j.b1[col], b1v = j.b1[col + 1];
                if (j.b2) { b0 += j.b2[col]; b1v += j.b2[col + 1]; }
                float v0 = acc[mf][nf][0] + b0;
                float v1 = acc[mf][nf][1] + b1v;
                float v2 = acc[mf][nf][2] + b0;
                float v3 = acc[mf][nf][3] + b1v;
                if (RELU) {
                    v0 = fmaxf(v0, 0.f); v1 = fmaxf(v1, 0.f);
                    v2 = fmaxf(v2, 0.f); v3 = fmaxf(v3, 0.f);
                }
                float2* p0 = (float2*)&j.C[(size_t)row * j.N + col];
                float2* p1 = (float2*)&j.C[(size_t)(row + 8) * j.N + col];
                *p0 = make_float2(v0, v1);
                *p1 = make_float2(v2, v3);
            }
        }
    }
}

// ---------------------------------------------------------------------------
// Fused attention scores (tf32 MMA + relu + Wa2 reduction).
// grid = (S, 3): blockIdx.y picks a chunk of n-tiles (5,5,5 of 15 x 128).
// spart[chunk][s][b] partial results; softmax sums the 3 chunks + ba2.
// ---------------------------------------------------------------------------
__global__ __launch_bounds__(256) void mma_scores_kernel(
    const float* __restrict__ h, const float* __restrict__ Wa1h,
    const float* __restrict__ qpart, const float* __restrict__ Wa2,
    float* __restrict__ spart)
{
    __shared__ uint32_t As[64][36];
    __shared__ uint32_t Ws[128][36];
    __shared__ float red[64][17];

    const int s = blockIdx.x, chunk = blockIdx.y;
    const int tid = threadIdx.x, lane = tid & 31, wid = tid >> 5;
    const int warpM = wid >> 2, warpN = wid & 3;
    const int g = lane >> 2, t = lane & 3;
    const float* A = h + (size_t)s * B_ * E_;

    float sacc[2][2] = {};

    const int tile0 = chunk * 5;
    const int tile1 = (tile0 + 5 < 15) ? (tile0 + 5) : 15;

    for (int tile = tile0; tile < tile1; tile++) {
        const int nb = tile * 128;
        float acc[2][4][4];
        #pragma unroll
        for (int mf = 0; mf < 2; mf++)
            #pragma unroll
            for (int nf = 0; nf < 4; nf++)
                #pragma unroll
                for (int i = 0; i < 4; i++) acc[mf][nf][i] = 0.f;

        gemm_segment<128>(A, Wa1h, E_, DE_, D_, nb, As, Ws, acc);

        #pragma unroll
        for (int mf = 0; mf < 2; mf++) {
            const int row = warpM * 32 + mf * 16 + g;
            #pragma unroll
            for (int nf = 0; nf < 4; nf++) {
                const int col = nb + warpN * 32 + nf * 8 + 2 * t;
                if (col < D_) {
                    const float w0 = Wa2[col], w1 = Wa2[col + 1];
                    const float q0 = qpart[(size_t)row * D_ + col];
                    const float q1 = qpart[(size_t)row * D_ + col + 1];
                    const float q2 = qpart[(size_t)(row + 8) * D_ + col];
                    const float q3 = qpart[(size_t)(row + 8) * D_ + col + 1];
                    sacc[mf][0] += fmaxf(acc[mf][nf][0] + q0, 0.f) * w0
                                 + fmaxf(acc[mf][nf][1] + q1, 0.f) * w1;
                    sacc[mf][1] += fmaxf(acc[mf][nf][2] + q2, 0.f) * w0
                                 + fmaxf(acc[mf][nf][3] + q3, 0.f) * w1;
                }
            }
        }
    }

    #pragma unroll
    for (int mf = 0; mf < 2; mf++)
        #pragma unroll
        for (int hh = 0; hh < 2; hh++) {
            const int row = warpM * 32 + mf * 16 + g + hh * 8;
            red[row][warpN * 4 + t] = sacc[mf][hh];
        }
    __syncthreads();
    if (tid < 64) {
        float a = 0.f;
        #pragma unroll
        for (int c = 0; c < 16; c++) a += red[tid][c];
        spart[(size_t)chunk * S_ * B_ + (size_t)s * B_ + tid] = a;
    }
}

// ---------------------------------------------------------------------------
// Small kernels
// ---------------------------------------------------------------------------
__global__ void havg_kernel(const float* __restrict__ h, float* __restrict__ havg)
{
    int b = blockIdx.x;
    int e = blockIdx.y * 256 + threadIdx.x;
    float s = 0.f;
    for (int si = 0; si < S_; si++)
        s += h[((size_t)si * B_ + b) * E_ + e];
    havg[(size_t)b * E_ + e] = s * (1.f / (float)S_);
}

__global__ __launch_bounds__(256) void softmax_beta_kernel(
    const float* __restrict__ spart, const float* __restrict__ h0,
    const float* __restrict__ Wb, const float* __restrict__ bb,
    const float* __restrict__ ba2,
    float* __restrict__ aw_out, float* __restrict__ beta)
{
    int b = blockIdx.x, tid = threadIdx.x;
    __shared__ float sm[256];

    float p = 0.f;
    for (int d = tid; d < D_; d += 256) p = fmaf(h0[(size_t)b * D_ + d], Wb[d], p);
    sm[tid] = p; __syncthreads();
    for (int o = 128; o > 0; o >>= 1) { if (tid < o) sm[tid] += sm[tid + o]; __syncthreads(); }
    if (tid == 0) beta[b] = 1.f / (1.f + expf(-(sm[0] + bb[0])));
    __syncthreads();

    float v = -3.4e38f;
    if (tid < S_) {
        size_t idx = (size_t)tid * B_ + b;
        v = spart[idx] + spart[(size_t)S_ * B_ + idx] + spart[2 * (size_t)S_ * B_ + idx] + ba2[0];
    }
    sm[tid] = v; __syncthreads();
    for (int o = 128; o > 0; o >>= 1) { if (tid < o) sm[tid] = fmaxf(sm[tid], sm[tid + o]); __syncthreads(); }
    float mx = sm[0]; __syncthreads();
    float e = (tid < S_) ? expf(v - mx) : 0.f;
    sm[tid] = e; __syncthreads();
    for (int o = 128; o > 0; o >>= 1) { if (tid < o) sm[tid] += sm[tid + o]; __syncthreads(); }
    float inv = 1.f / sm[0];
    if (tid < S_) aw_out[(size_t)tid * B_ + b] = e * inv;
}

__global__ void ctx_kernel(const float* __restrict__ h, const float* __restrict__ aw,
                           const float* __restrict__ beta, float* __restrict__ ctx)
{
    int b = blockIdx.x;
    int e = blockIdx.y * 256 + threadIdx.x;
    float s = 0.f;
    for (int si = 0; si < S_; si++)
        s = fmaf(aw[(size_t)si * B_ + b], h[((size_t)si * B_ + b) * E_ + e], s);
    ctx[(size_t)b * E_ + e] = s * beta[b];
}

__global__ __launch_bounds__(256) void argmax_kernel(const float* __restrict__ y, int* __restrict__ amax)
{
    int b = blockIdx.x, tid = threadIdx.x;
    float bm = -3.4e38f; int bi = 0;
    for (int i = tid; i < V_; i += 256) {
        float v = y[(size_t)b * V_ + i];
        if (v > bm) { bm = v; bi = i; }
    }
    __shared__ float sv[256];
    __shared__ int si_[256];
    sv[tid] = bm; si_[tid] = bi; __syncthreads();
    for (int o = 128; o > 0; o >>= 1) {
        if (tid < o) {
            if (sv[tid + o] > sv[tid] || (sv[tid + o] == sv[tid] && si_[tid + o] < si_[tid])) {
                sv[tid] = sv[tid + o]; si_[tid] = si_[tid + o];
            }
        }
        __syncthreads();
    }
    if (tid == 0) amax[b] = si_[0];
}

__global__ void xbuild_kernel(const float* __restrict__ emb, const int* __restrict__ Etm1,
                              const float* __restrict__ ctx, float* __restrict__ x)
{
    int b = blockIdx.x;
    int i = blockIdx.y * 256 + threadIdx.x;
    if (i < W_) x[(size_t)b * WE_ + i] = emb[(size_t)Etm1[b] * W_ + i];
    else        x[(size_t)b * WE_ + i] = ctx[(size_t)b * E_ + (i - W_)];
}

__global__ void lstm_kernel(const float* __restrict__ gates, const float* __restrict__ c0,
                            float* __restrict__ out, float* __restrict__ z)
{
    int b = blockIdx.x;
    int d = blockIdx.y * 256 + threadIdx.x;
    if (d >= D_) return;
    const float* g = gates + (size_t)b * 4 * D_;
    float ig = 1.f / (1.f + expf(-g[d]));
    float fg = 1.f / (1.f + expf(-g[D_ + d]));
    float gg = tanhf(g[2 * D_ + d]);
    float og = 1.f / (1.f + expf(-g[3 * D_ + d]));
    float c = fmaf(fg, c0[(size_t)b * D_ + d], ig * gg);
    float ht = og * tanhf(c);
    out[(size_t)B_ * V_ + (size_t)b * D_ + d] = ht;
    out[(size_t)B_ * V_ + (size_t)B_ * D_ + (size_t)b * D_ + d] = c;
    z[(size_t)b * DWE_ + d] = ht;
}

__global__ void zbuild_kernel(const float* __restrict__ emb, const int* __restrict__ amax,
                              const float* __restrict__ ctx, float* __restrict__ z)
{
    int b = blockIdx.x;
    int i = blockIdx.y * 256 + threadIdx.x;
    if (i < W_) z[(size_t)b * DWE_ + D_ + i] = emb[(size_t)amax[b] * W_ + i];
    else        z[(size_t)b * DWE_ + D_ + i] = ctx[(size_t)b * E_ + (i - W_)];
}

// ---------------------------------------------------------------------------
// Launch
// ---------------------------------------------------------------------------
static inline Job mkjob(const float* A1, const float* W1, int K1, int ldw1,
                        const float* b1, float* C, int N,
                        const float* A2 = nullptr, const float* W2 = nullptr,
                        int K2 = 0, int ldw2 = 0, const float* b2 = nullptr)
{
    Job j;
    j.A1 = A1; j.W1 = W1; j.K1 = K1; j.ldw1 = ldw1;
    j.A2 = A2; j.W2 = W2; j.K2 = K2; j.ldw2 = ldw2;
    j.b1 = b1; j.b2 = b2; j.C = C; j.N = N;
    return j;
}

extern "C" void kernel_launch(void* const* d_in, const int* in_sizes, int n_in,
                              void* d_out, int out_size)
{
    const int*   E_tm1 = (const int*)d_in[0];
    const float* y_tm1 = (const float*)d_in[1];
    const float* h     = (const float*)d_in[2];
    const float* emb   = (const float*)d_in[3];
    const float* W_ih  = (const float*)d_in[4];
    const float* b_ih  = (const float*)d_in[5];
    const float* W_hh  = (const float*)d_in[6];
    const float* b_hh  = (const float*)d_in[7];
    const float* W_out = (const float*)d_in[8];
    const float* b_out = (const float*)d_in[9];
    const float* Wh1 = (const float*)d_in[10]; const float* bh1 = (const float*)d_in[11];
    const float* Wh2 = (const float*)d_in[12]; const float* bh2 = (const float*)d_in[13];
    const float* Wc1 = (const float*)d_in[14]; const float* bc1 = (const float*)d_in[15];
    const float* Wc2 = (const float*)d_in[16]; const float* bc2 = (const float*)d_in[17];
    const float* Wa1 = (const float*)d_in[18]; const float* ba1 = (const float*)d_in[19];
    const float* Wa2 = (const float*)d_in[20]; const float* ba2 = (const float*)d_in[21];
    const float* Wb  = (const float*)d_in[22]; const float* bb  = (const float*)d_in[23];
    float* out = (float*)d_out;

    Scratch* s = nullptr;
    cudaGetSymbolAddress((void**)&s, g_s);

    const int GN_D  = (D_ + 63) / 64;          // 29
    const int GN_4D = (4 * D_ + 63) / 64;      // 113
    const int GN_V  = V_ / 128;                // 250

    // 1. encoder mean
    havg_kernel<<<dim3(B_, E_ / 256), 256>>>(h, s->havg);

    // 2. init-state MLPs: layer 1 fused (relu), layer 2 fused
    {
        Job2 jj; jj.j[0] = mkjob(s->havg, Wh1, E_, E_, bh1, s->t1, D_);
                 jj.j[1] = mkjob(s->havg, Wc1, E_, E_, bc1, s->t2, D_);
        mma_gemm_kernel<64, true><<<dim3(GN_D, 2), 256>>>(jj);
    }
    {
        Job2 jj; jj.j[0] = mkjob(s->t1, Wh2, D_, D_, bh2, s->h0, D_);
                 jj.j[1] = mkjob(s->t2, Wc2, D_, D_, bc2, s->c0, D_);
        mma_gemm_kernel<64, false><<<dim3(GN_D, 2), 256>>>(jj);
    }

    // 3. attention query part: h0 @ Wa1[:, :D]^T + ba1
    {
        Job2 jj; jj.j[0] = mkjob(s->h0, Wa1, D_, DE_, ba1, s->qpart, D_);
                 jj.j[1] = jj.j[0];
        mma_gemm_kernel<64, false><<<dim3(GN_D, 1), 256>>>(jj);
    }

    // 4. fused scores GEMM (key part), n-split 3
    mma_scores_kernel<<<dim3(S_, 3), 256>>>(h, Wa1 + D_, s->qpart, Wa2, s->spart);

    // 5. argmax of y_tm1 (independent)
    argmax_kernel<<<B_, 256>>>(y_tm1, s->amax);

    // 6. softmax over S + beta gate
    float* aw_out = out + (size_t)B_ * V_ + 2 * (size_t)B_ * D_;
    softmax_beta_kernel<<<B_, 256>>>(s->spart, s->h0, Wb, bb, ba2, aw_out, s->beta);

    // 7. context (scaled by beta)
    ctx_kernel<<<dim3(B_, E_ / 256), 256>>>(h, aw_out, s->beta, s->ctx);

    // 8. LSTM input + fused gates GEMM (dual segment, both biases)
    xbuild_kernel<<<dim3(B_, WE_ / 256), 256>>>(emb, E_tm1, s->ctx, s->x);
    {
        Job2 jj; jj.j[0] = mkjob(s->x, W_ih, WE_, WE_, b_ih, s->gates, 4 * D_,
                                 s->h0, W_hh, D_, D_, b_hh);
                 jj.j[1] = jj.j[0];
        mma_gemm_kernel<64, false><<<dim3(GN_4D, 1), 256>>>(jj);
    }

    // 9. LSTM pointwise
    lstm_kernel<<<dim3(B_, (D_ + 255) / 256), 256>>>(s->gates, s->c0, out, s->z);

    // 10. z = [h_t, y_emb, ctx]
    zbuild_kernel<<<dim3(B_, WE_ / 256), 256>>>(emb, s->amax, s->ctx, s->z);

    // 11. logits
    {
        Job2 jj; jj.j[0] = mkjob(s->z, W_out, DWE_, DWE_, b_out, out, V_);
                 jj.j[1] = jj.j[0];
        mma_gemm_kernel<128, false><<<dim3(GN_V, 1), 256>>>(jj);
    }
}

// round 3
// speedup vs baseline: 3.2506x; 1.1475x over previous
#include <cuda_runtime.h>
#include <math.h>
#include <stdint.h>

#define S_ 196
#define B_ 64
#define E_ 1024
#define D_ 1800
#define W_ 512
#define V_ 32000
#define WE_ (W_ + E_)       // 1536
#define DE_ (D_ + E_)       // 2824
#define DWE_ (D_ + W_ + E_) // 3336

// ---------------------------------------------------------------------------
// Scratch
// ---------------------------------------------------------------------------
struct Scratch {
    float havg[B_ * E_];
    float t1[B_ * D_];
    float t2[B_ * D_];
    float h0[B_ * D_];
    float c0[B_ * D_];
    float qpart[B_ * D_];
    float spart[3 * S_ * B_];
    float beta[B_];
    float ctx[B_ * E_];
    float x[B_ * WE_];
    float z[B_ * DWE_];
    int   amax[B_];
    float skp[2][3][B_ * D_];       // split-K partials (2 jobs x up to 3 slices)
    float gp0[B_ * 4 * D_];         // gates partial: x @ W_ih
    float gp1[B_ * 4 * D_];         // gates partial: h0 @ W_hh
};
__device__ Scratch g_s;

// ---------------------------------------------------------------------------
// tf32 helpers
// ---------------------------------------------------------------------------
__device__ __forceinline__ uint32_t f2tf32(float f) {
    uint32_t u;
    asm("cvt.rna.tf32.f32 %0, %1;" : "=r"(u) : "f"(f));
    return u;
}

__device__ __forceinline__ void mma_tf32(float (&c)[4], const uint32_t (&a)[4],
                                         const uint32_t b0, const uint32_t b1) {
    asm volatile(
        "mma.sync.aligned.m16n8k8.row.col.f32.tf32.tf32.f32 "
        "{%0,%1,%2,%3},{%4,%5,%6,%7},{%8,%9},{%0,%1,%2,%3};"
        : "+f"(c[0]), "+f"(c[1]), "+f"(c[2]), "+f"(c[3])
        : "r"(a[0]), "r"(a[1]), "r"(a[2]), "r"(a[3]), "r"(b0), "r"(b1));
}

// Packed smem: uint2 = (tf32 at k=ks*8+t, tf32 at k=ks*8+t+4). Row stride 18
// uint2 (144 B): 16-byte aligned (STS.128-able) and bank-staggered (+4 words/row).
#define SPAD 18

// ---------------------------------------------------------------------------
// One K-segment (tile range [t0,t1), 32 k per tile) of a 64 x BN tile.
// A: [64, K] row-major. W: [N, K] row-major, row stride ldw.
// ---------------------------------------------------------------------------
template<int BN>
__device__ __forceinline__ void seg64(
    const float* __restrict__ A, const float* __restrict__ W,
    const int K, const int ldw, const int N, const int nb,
    const int t0, const int t1,
    uint2 As[64][SPAD], uint2 Ws[BN][SPAD],
    float (&acc)[2][BN / 32][4])
{
    constexpr int NF  = BN / 32;
    constexpr int WPT = (BN == 64) ? 8 : 16;
    const int tid  = threadIdx.x;
    const int lane = tid & 31, wid = tid >> 5;
    const int warpM = wid >> 2, warpN = wid & 3;
    const int g = lane >> 2, t = lane & 3;

    const int am  = tid & 63, akg = (tid >> 6) * 8;
    const int wn  = (BN == 64) ? (tid & 63) : (tid & 127);
    const int wkg = (BN == 64) ? ((tid >> 6) * 8) : ((tid >> 7) * 16);
    const bool wvalid = (nb + wn) < N;
    const float* Abase = A + (size_t)am * K;
    const float* Wbase = W + (size_t)(nb + wn) * ldw;

    float ra[8];
    float rw[WPT];

    auto loadA = [&](int ti) {
        const int k0 = ti * 32 + akg;
        if (k0 + 8 <= K) {
            float4 v0 = *(const float4*)(Abase + k0);
            float4 v1 = *(const float4*)(Abase + k0 + 4);
            ra[0] = v0.x; ra[1] = v0.y; ra[2] = v0.z; ra[3] = v0.w;
            ra[4] = v1.x; ra[5] = v1.y; ra[6] = v1.z; ra[7] = v1.w;
        } else {
            #pragma unroll
            for (int i = 0; i < 8; i++)
                ra[i] = (k0 + i < K) ? Abase[k0 + i] : 0.f;
        }
    };
    auto loadW = [&](int ti) {
        const int k0 = ti * 32 + wkg;
        if (wvalid && k0 + WPT <= K) {
            #pragma unroll
            for (int i = 0; i < WPT / 4; i++) {
                float4 v = *(const float4*)(Wbase + k0 + i * 4);
                rw[i * 4 + 0] = v.x; rw[i * 4 + 1] = v.y;
                rw[i * 4 + 2] = v.z; rw[i * 4 + 3] = v.w;
            }
        } else {
            #pragma unroll
            for (int i = 0; i < WPT; i++)
                rw[i] = (wvalid && (k0 + i) < K) ? Wbase[k0 + i] : 0.f;
        }
    };

    loadA(t0);
    loadW(t0);

    for (int ti = t0; ti < t1; ti++) {
        __syncthreads();
        {
            const int ks = akg >> 3;
            uint4* p = (uint4*)&As[am][ks * 4];
            p[0] = make_uint4(f2tf32(ra[0]), f2tf32(ra[4]), f2tf32(ra[1]), f2tf32(ra[5]));
            p[1] = make_uint4(f2tf32(ra[2]), f2tf32(ra[6]), f2tf32(ra[3]), f2tf32(ra[7]));
        }
        {
            #pragma unroll
            for (int h8 = 0; h8 < WPT / 8; h8++) {
                const int ks = (wkg >> 3) + h8;
                const float* r = rw + h8 * 8;
                uint4* p = (uint4*)&Ws[wn][ks * 4];
                p[0] = make_uint4(f2tf32(r[0]), f2tf32(r[4]), f2tf32(r[1]), f2tf32(r[5]));
                p[1] = make_uint4(f2tf32(r[2]), f2tf32(r[6]), f2tf32(r[3]), f2tf32(r[7]));
            }
        }
        __syncthreads();

        if (ti + 1 < t1) { loadA(ti + 1); loadW(ti + 1); }

        #pragma unroll
        for (int ks = 0; ks < 4; ks++) {
            uint32_t a[2][4];
            #pragma unroll
            for (int mf = 0; mf < 2; mf++) {
                const int r = warpM * 32 + mf * 16 + g;
                uint2 lo = As[r][ks * 4 + t];
                uint2 hi = As[r + 8][ks * 4 + t];
                a[mf][0] = lo.x; a[mf][1] = hi.x;
                a[mf][2] = lo.y; a[mf][3] = hi.y;
            }
            #pragma unroll
            for (int nf = 0; nf < NF; nf++) {
                const int n = warpN * (BN / 4) + nf * 8 + g;
                uint2 b = Ws[n][ks * 4 + t];
                #pragma unroll
                for (int mf = 0; mf < 2; mf++)
                    mma_tf32(acc[mf][nf], a[mf], b.x, b.y);
            }
        }
    }
}

// ---------------------------------------------------------------------------
// Full GEMM (with bias/act, optional second K-segment)
// ---------------------------------------------------------------------------
struct Job {
    const float* A1; const float* W1; int K1; int ldw1;
    const float* A2; const float* W2; int K2; int ldw2;
    const float* b1; const float* b2;
    float* C; int N;
};
struct Job2 { Job j[2]; };

template<int BN, bool RELU>
__global__ __launch_bounds__(256) void mma_gemm_kernel(Job2 jobs)
{
    constexpr int NF = BN / 32;
    __shared__ uint2 As[64][SPAD];
    __shared__ uint2 Ws[BN][SPAD];

    const Job j = jobs.j[blockIdx.y];
    const int nb = blockIdx.x * BN;
    if (nb >= j.N) return;

    float acc[2][NF][4] = {};

    seg64<BN>(j.A1, j.W1, j.K1, j.ldw1, j.N, nb, 0, (j.K1 + 31) >> 5, As, Ws, acc);
    if (j.A2)
        seg64<BN>(j.A2, j.W2, j.K2, j.ldw2, j.N, nb, 0, (j.K2 + 31) >> 5, As, Ws, acc);

    const int tid = threadIdx.x, lane = tid & 31, wid = tid >> 5;
    const int warpM = wid >> 2, warpN = wid & 3;
    const int g = lane >> 2, t = lane & 3;

    #pragma unroll
    for (int mf = 0; mf < 2; mf++) {
        const int row = warpM * 32 + mf * 16 + g;
        #pragma unroll
        for (int nf = 0; nf < NF; nf++) {
            const int col = nb + warpN * (BN / 4) + nf * 8 + 2 * t;
            if (col < j.N) {
                float b0 = j.b1[col], b1v = j.b1[col + 1];
                if (j.b2) { b0 += j.b2[col]; b1v += j.b2[col + 1]; }
                float v0 = acc[mf][nf][0] + b0;
                float v1 = acc[mf][nf][1] + b1v;
                float v2 = acc[mf][nf][2] + b0;
                float v3 = acc[mf][nf][3] + b1v;
                if (RELU) {
                    v0 = fmaxf(v0, 0.f); v1 = fmaxf(v1, 0.f);
                    v2 = fmaxf(v2, 0.f); v3 = fmaxf(v3, 0.f);
                }
                *(float2*)&j.C[(size_t)row * j.N + col]       = make_float2(v0, v1);
                *(float2*)&j.C[(size_t)(row + 8) * j.N + col] = make_float2(v2, v3);
            }
        }
    }
}

// ---------------------------------------------------------------------------
// Split-K GEMM: partials only (no bias/act). grid = (tiles, jobs, KS).
// ---------------------------------------------------------------------------
struct SKJob { const float* A; const float* W; int K; int ldw; int N; float* Cpart; };
struct SKJob2 { SKJob j[2]; };

template<int BN>
__global__ __launch_bounds__(256) void sk_gemm_kernel(SKJob2 jobs)
{
    constexpr int NF = BN / 32;
    __shared__ uint2 As[64][SPAD];
    __shared__ uint2 Ws[BN][SPAD];

    const SKJob j = jobs.j[blockIdx.y];
    const int nb = blockIdx.x * BN;
    if (nb >= j.N) return;

    const int tiles = (j.K + 31) >> 5;
    const int KS = gridDim.z, kz = blockIdx.z;
    const int tpk = (tiles + KS - 1) / KS;
    const int t0 = kz * tpk;
    const int t1 = (t0 + tpk < tiles) ? (t0 + tpk) : tiles;

    float acc[2][NF][4] = {};
    if (t0 < t1)
        seg64<BN>(j.A, j.W, j.K, j.ldw, j.N, nb, t0, t1, As, Ws, acc);

    float* C = j.Cpart + (size_t)kz * 64 * j.N;
    const int tid = threadIdx.x, lane = tid & 31, wid = tid >> 5;
    const int warpM = wid >> 2, warpN = wid & 3;
    const int g = lane >> 2, t = lane & 3;

    #pragma unroll
    for (int mf = 0; mf < 2; mf++) {
        const int row = warpM * 32 + mf * 16 + g;
        #pragma unroll
        for (int nf = 0; nf < NF; nf++) {
            const int col = nb + warpN * (BN / 4) + nf * 8 + 2 * t;
            if (col < j.N) {
                *(float2*)&C[(size_t)row * j.N + col]       = make_float2(acc[mf][nf][0], acc[mf][nf][1]);
                *(float2*)&C[(size_t)(row + 8) * j.N + col] = make_float2(acc[mf][nf][2], acc[mf][nf][3]);
            }
        }
    }
}

// Reduce split-K partials + bias (+relu). grid = (blocks, jobs)
struct RJob { const float* part; const float* bias; float* out; };
struct RJob2 { RJob j[2]; };

template<int KS, bool RELU>
__global__ __launch_bounds__(256) void sk_reduce_kernel(RJob2 jobs, int N, int total)
{
    const RJob j = jobs.j[blockIdx.y];
    int idx = blockIdx.x * 256 + threadIdx.x;
    if (idx >= total) return;
    int n = idx % N;
    float v = j.bias[n];
    #pragma unroll
    for (int k = 0; k < KS; k++) v += j.part[(size_t)k * total + idx];
    if (RELU) v = fmaxf(v, 0.f);
    j.out[idx] = v;
}

// ---------------------------------------------------------------------------
// Fused attention scores. BM=128 (two seq positions per block), BN=128.
// grid = (98, 3): blockIdx.y = chunk of 5 n-tiles.
// ---------------------------------------------------------------------------
__global__ __launch_bounds__(256) void mma_scores_kernel(
    const float* __restrict__ h, const float* __restrict__ Wa1h,
    const float* __restrict__ qpart, const float* __restrict__ Wa2,
    float* __restrict__ spart)
{
    __shared__ uint2 As[128][SPAD];
    __shared__ uint2 Ws[128][SPAD];
    __shared__ float red[128][17];

    const int spair = blockIdx.x, chunk = blockIdx.y;
    const int tid = threadIdx.x, lane = tid & 31, wid = tid >> 5;
    const int warpR = wid >> 2, warpC = wid & 3;
    const int g = lane >> 2, t = lane & 3;

    const int lrow = tid & 127;                 // loader row (A and W)
    const int khalf = (tid >> 7) * 16;          // 2 threads per row, 16 k each
    const float* Abase = h + ((size_t)spair * 128 + lrow) * E_;

    float sacc[4][2] = {};

    const int tile0 = chunk * 5;
    for (int tile = tile0; tile < tile0 + 5; tile++) {
        const int nb = tile * 128;
        const bool wvalid = (nb + lrow) < D_;
        const float* Wbase = Wa1h + (size_t)(nb + lrow) * DE_;

        float acc[4][4][4] = {};
        float ra[16], rw[16];

        auto loadA = [&](int ti) {
            const int k0 = ti * 32 + khalf;
            #pragma unroll
            for (int i = 0; i < 4; i++) {
                float4 v = *(const float4*)(Abase + k0 + i * 4);
                ra[i * 4 + 0] = v.x; ra[i * 4 + 1] = v.y;
                ra[i * 4 + 2] = v.z; ra[i * 4 + 3] = v.w;
            }
        };
        auto loadW = [&](int ti) {
            const int k0 = ti * 32 + khalf;
            if (wvalid) {
                #pragma unroll
                for (int i = 0; i < 4; i++) {
                    float4 v = *(const float4*)(Wbase + k0 + i * 4);
                    rw[i * 4 + 0] = v.x; rw[i * 4 + 1] = v.y;
                    rw[i * 4 + 2] = v.z; rw[i * 4 + 3] = v.w;
                }
            } else {
                #pragma unroll
                for (int i = 0; i < 16; i++) rw[i] = 0.f;
            }
        };

        loadA(0); loadW(0);

        for (int ti = 0; ti < E_ / 32; ti++) {
            __syncthreads();
            #pragma unroll
            for (int h8 = 0; h8 < 2; h8++) {
                const int ks = (khalf >> 3) + h8;
                const float* r = ra + h8 * 8;
                uint4* p = (uint4*)&As[lrow][ks * 4];
                p[0] = make_uint4(f2tf32(r[0]), f2tf32(r[4]), f2tf32(r[1]), f2tf32(r[5]));
                p[1] = make_uint4(f2tf32(r[2]), f2tf32(r[6]), f2tf32(r[3]), f2tf32(r[7]));
                const float* w = rw + h8 * 8;
                uint4* q = (uint4*)&Ws[lrow][ks * 4];
                q[0] = make_uint4(f2tf32(w[0]), f2tf32(w[4]), f2tf32(w[1]), f2tf32(w[5]));
                q[1] = make_uint4(f2tf32(w[2]), f2tf32(w[6]), f2tf32(w[3]), f2tf32(w[7]));
            }
            __syncthreads();

            if (ti + 1 < E_ / 32) { loadA(ti + 1); loadW(ti + 1); }

            #pragma unroll
            for (int ks = 0; ks < 4; ks++) {
                uint32_t a[4][4];
                #pragma unroll
                for (int mf = 0; mf < 4; mf++) {
                    const int r = warpR * 64 + mf * 16 + g;
                    uint2 lo = As[r][ks * 4 + t];
                    uint2 hi = As[r + 8][ks * 4 + t];
                    a[mf][0] = lo.x; a[mf][1] = hi.x;
                    a[mf][2] = lo.y; a[mf][3] = hi.y;
                }
                #pragma unroll
                for (int nf = 0; nf < 4; nf++) {
                    const int n = warpC * 32 + nf * 8 + g;
                    uint2 b = Ws[n][ks * 4 + t];
                    #pragma unroll
                    for (int mf = 0; mf < 4; mf++)
                        mma_tf32(acc[mf][nf], a[mf], b.x, b.y);
                }
            }
        }

        // epilogue: + qpart, relu, * Wa2, accumulate per-row
        #pragma unroll
        for (int mf = 0; mf < 4; mf++) {
            const int row = warpR * 64 + mf * 16 + g;
            const int b0r = row & 63, b1r = (row + 8) & 63;
            #pragma unroll
            for (int nf = 0; nf < 4; nf++) {
                const int col = nb + warpC * 32 + nf * 8 + 2 * t;
                if (col < D_) {
                    const float w0 = Wa2[col], w1 = Wa2[col + 1];
                    const float q0 = qpart[(size_t)b0r * D_ + col];
                    const float q1 = qpart[(size_t)b0r * D_ + col + 1];
                    const float q2 = qpart[(size_t)b1r * D_ + col];
                    const float q3 = qpart[(size_t)b1r * D_ + col + 1];
                    sacc[mf][0] += fmaxf(acc[mf][nf][0] + q0, 0.f) * w0
                                 + fmaxf(acc[mf][nf][1] + q1, 0.f) * w1;
                    sacc[mf][1] += fmaxf(acc[mf][nf][2] + q2, 0.f) * w0
                                 + fmaxf(acc[mf][nf][3] + q3, 0.f) * w1;
                }
            }
        }
    }

    __syncthreads();
    #pragma unroll
    for (int mf = 0; mf < 4; mf++) {
        const int row = warpR * 64 + mf * 16 + g;
        red[row][warpC * 4 + t]     = sacc[mf][0];
        red[row + 8][warpC * 4 + t] = sacc[mf][1];
    }
    __syncthreads();
    if (tid < 128) {
        float a = 0.f;
        #pragma unroll
        for (int c = 0; c < 16; c++) a += red[tid][c];
        const int s = spair * 2 + (tid >> 6);
        const int b = tid & 63;
        spart[(size_t)chunk * S_ * B_ + (size_t)s * B_ + b] = a;
    }
}

// ---------------------------------------------------------------------------
// Small kernels
// ---------------------------------------------------------------------------
__global__ void havg_kernel(const float* __restrict__ h, float* __restrict__ havg)
{
    int b = blockIdx.x;
    int e = blockIdx.y * 256 + threadIdx.x;
    float s = 0.f;
    for (int si = 0; si < S_; si++)
        s += h[((size_t)si * B_ + b) * E_ + e];
    havg[(size_t)b * E_ + e] = s * (1.f / (float)S_);
}

__global__ __launch_bounds__(256) void softmax_beta_kernel(
    const float* __restrict__ spart, const float* __restrict__ h0,
    const float* __restrict__ Wb, const float* __restrict__ bb,
    const float* __restrict__ ba2,
    float* __restrict__ aw_out, float* __restrict__ beta)
{
    int b = blockIdx.x, tid = threadIdx.x;
    __shared__ float sm[256];

    float p = 0.f;
    for (int d = tid; d < D_; d += 256) p = fmaf(h0[(size_t)b * D_ + d], Wb[d], p);
    sm[tid] = p; __syncthreads();
    for (int o = 128; o > 0; o >>= 1) { if (tid < o) sm[tid] += sm[tid + o]; __syncthreads(); }
    if (tid == 0) beta[b] = 1.f / (1.f + expf(-(sm[0] + bb[0])));
    __syncthreads();

    float v = -3.4e38f;
    if (tid < S_) {
        size_t idx = (size_t)tid * B_ + b;
        v = spart[idx] + spart[(size_t)S_ * B_ + idx] + spart[2 * (size_t)S_ * B_ + idx] + ba2[0];
    }
    sm[tid] = v; __syncthreads();
    for (int o = 128; o > 0; o >>= 1) { if (tid < o) sm[tid] = fmaxf(sm[tid], sm[tid + o]); __syncthreads(); }
    float mx = sm[0]; __syncthreads();
    float e = (tid < S_) ? expf(v - mx) : 0.f;
    sm[tid] = e; __syncthreads();
    for (int o = 128; o > 0; o >>= 1) { if (tid < o) sm[tid] += sm[tid + o]; __syncthreads(); }
    float inv = 1.f / sm[0];
    if (tid < S_) aw_out[(size_t)tid * B_ + b] = e * inv;
}

__global__ void ctx_kernel(const float* __restrict__ h, const float* __restrict__ aw,
                           const float* __restrict__ beta, float* __restrict__ ctx)
{
    int b = blockIdx.x;
    int e = blockIdx.y * 256 + threadIdx.x;
    float s = 0.f;
    for (int si = 0; si < S_; si++)
        s = fmaf(aw[(size_t)si * B_ + b], h[((size_t)si * B_ + b) * E_ + e], s);
    ctx[(size_t)b * E_ + e] = s * beta[b];
}

__global__ __launch_bounds__(256) void argmax_kernel(const float* __restrict__ y, int* __restrict__ amax)
{
    int b = blockIdx.x, tid = threadIdx.x;
    float bm = -3.4e38f; int bi = 0;
    for (int i = tid; i < V_; i += 256) {
        float v = y[(size_t)b * V_ + i];
        if (v > bm) { bm = v; bi = i; }
    }
    __shared__ float sv[256];
    __shared__ int si_[256];
    sv[tid] = bm; si_[tid] = bi; __syncthreads();
    for (int o = 128; o > 0; o >>= 1) {
        if (tid < o) {
            if (sv[tid + o] > sv[tid] || (sv[tid + o] == sv[tid] && si_[tid + o] < si_[tid])) {
                sv[tid] = sv[tid + o]; si_[tid] = si_[tid + o];
            }
        }
        __syncthreads();
    }
    if (tid == 0) amax[b] = si_[0];
}

__global__ void xbuild_kernel(const float* __restrict__ emb, const int* __restrict__ Etm1,
                              const float* __restrict__ ctx, float* __restrict__ x)
{
    int b = blockIdx.x;
    int i = blockIdx.y * 256 + threadIdx.x;
    if (i < W_) x[(size_t)b * WE_ + i] = emb[(size_t)Etm1[b] * W_ + i];
    else        x[(size_t)b * WE_ + i] = ctx[(size_t)b * E_ + (i - W_)];
}

// LSTM pointwise; also reduces the two gate partials + both biases.
__global__ void lstm_kernel(const float* __restrict__ gp0, const float* __restrict__ gp1,
                            const float* __restrict__ b_ih, const float* __restrict__ b_hh,
                            const float* __restrict__ c0,
                            float* __restrict__ out, float* __restrict__ z)
{
    int b = blockIdx.x;
    int d = blockIdx.y * 256 + threadIdx.x;
    if (d >= D_) return;
    const size_t base = (size_t)b * 4 * D_;
    float gi = gp0[base + d]           + gp1[base + d]           + b_ih[d]           + b_hh[d];
    float gf = gp0[base + D_ + d]      + gp1[base + D_ + d]      + b_ih[D_ + d]      + b_hh[D_ + d];
    float gg = gp0[base + 2 * D_ + d]  + gp1[base + 2 * D_ + d]  + b_ih[2 * D_ + d]  + b_hh[2 * D_ + d];
    float go = gp0[base + 3 * D_ + d]  + gp1[base + 3 * D_ + d]  + b_ih[3 * D_ + d]  + b_hh[3 * D_ + d];
    float ig = 1.f / (1.f + expf(-gi));
    float fg = 1.f / (1.f + expf(-gf));
    float gt = tanhf(gg);
    float og = 1.f / (1.f + expf(-go));
    float c = fmaf(fg, c0[(size_t)b * D_ + d], ig * gt);
    float ht = og * tanhf(c);
    out[(size_t)B_ * V_ + (size_t)b * D_ + d] = ht;
    out[(size_t)B_ * V_ + (size_t)B_ * D_ + (size_t)b * D_ + d] = c;
    z[(size_t)b * DWE_ + d] = ht;
}

__global__ void zbuild_kernel(const float* __restrict__ emb, const int* __restrict__ amax,
                              const float* __restrict__ ctx, float* __restrict__ z)
{
    int b = blockIdx.x;
    int i = blockIdx.y * 256 + threadIdx.x;
    if (i < W_) z[(size_t)b * DWE_ + D_ + i] = emb[(size_t)amax[b] * W_ + i];
    else        z[(size_t)b * DWE_ + D_ + i] = ctx[(size_t)b * E_ + (i - W_)];
}

// ---------------------------------------------------------------------------
// Launch
// ---------------------------------------------------------------------------
extern "C" void kernel_launch(void* const* d_in, const int* in_sizes, int n_in,
                              void* d_out, int out_size)
{
    const int*   E_tm1 = (const int*)d_in[0];
    const float* y_tm1 = (const float*)d_in[1];
    const float* h     = (const float*)d_in[2];
    const float* emb   = (const float*)d_in[3];
    const float* W_ih  = (const float*)d_in[4];
    const float* b_ih  = (const float*)d_in[5];
    const float* W_hh  = (const float*)d_in[6];
    const float* b_hh  = (const float*)d_in[7];
    const float* W_out = (const float*)d_in[8];
    const float* b_out = (const float*)d_in[9];
    const float* Wh1 = (const float*)d_in[10]; const float* bh1 = (const float*)d_in[11];
    const float* Wh2 = (const float*)d_in[12]; const float* bh2 = (const float*)d_in[13];
    const float* Wc1 = (const float*)d_in[14]; const float* bc1 = (const float*)d_in[15];
    const float* Wc2 = (const float*)d_in[16]; const float* bc2 = (const float*)d_in[17];
    const float* Wa1 = (const float*)d_in[18]; const float* ba1 = (const float*)d_in[19];
    const float* Wa2 = (const float*)d_in[20]; const float* ba2 = (const float*)d_in[21];
    const float* Wb  = (const float*)d_in[22]; const float* bb  = (const float*)d_in[23];
    float* out = (float*)d_out;

    Scratch* s = nullptr;
    cudaGetSymbolAddress((void**)&s, g_s);

    const int GN_D   = (D_ + 63) / 64;          // 29
    const int GN_4D  = (4 * D_ + 127) / 128;    // 57
    const int GN_V   = V_ / 128;                // 250
    const int RED_BLK = (B_ * D_ + 255) / 256;  // 450

    // 1. encoder mean
    havg_kernel<<<dim3(B_, E_ / 256), 256>>>(h, s->havg);

    // 2. init-state MLPs (split-K for latency)
    {   // layer 1 (K=1024, KS=2), relu
        SKJob2 jj;
        jj.j[0] = {s->havg, Wh1, E_, E_, D_, s->skp[0][0]};
        jj.j[1] = {s->havg, Wc1, E_, E_, D_, s->skp[1][0]};
        sk_gemm_kernel<64><<<dim3(GN_D, 2, 2), 256>>>(jj);
        RJob2 rr; rr.j[0] = {s->skp[0][0], bh1, s->t1};
                  rr.j[1] = {s->skp[1][0], bc1, s->t2};
        sk_reduce_kernel<2, true><<<dim3(RED_BLK, 2), 256>>>(rr, D_, B_ * D_);
    }
    {   // layer 2 (K=1800, KS=3)
        SKJob2 jj;
        jj.j[0] = {s->t1, Wh2, D_, D_, D_, s->skp[0][0]};
        jj.j[1] = {s->t2, Wc2, D_, D_, D_, s->skp[1][0]};
        sk_gemm_kernel<64><<<dim3(GN_D, 2, 3), 256>>>(jj);
        RJob2 rr; rr.j[0] = {s->skp[0][0], bh2, s->h0};
                  rr.j[1] = {s->skp[1][0], bc2, s->c0};
        sk_reduce_kernel<3, false><<<dim3(RED_BLK, 2), 256>>>(rr, D_, B_ * D_);
    }

    // 3. attention query part: h0 @ Wa1[:, :D]^T + ba1 (KS=3)
    {
        SKJob2 jj;
        jj.j[0] = {s->h0, Wa1, D_, DE_, D_, s->skp[0][0]};
        jj.j[1] = jj.j[0];
        sk_gemm_kernel<64><<<dim3(GN_D, 1, 3), 256>>>(jj);
        RJob2 rr; rr.j[0] = {s->skp[0][0], ba1, s->qpart};
                  rr.j[1] = rr.j[0];
        sk_reduce_kernel<3, false><<<dim3(RED_BLK, 1), 256>>>(rr, D_, B_ * D_);
    }

    // 4. fused scores GEMM (BM=128, n-split 3)
    mma_scores_kernel<<<dim3(S_ / 2, 3), 256>>>(h, Wa1 + D_, s->qpart, Wa2, s->spart);

    // 5. argmax of y_tm1
    argmax_kernel<<<B_, 256>>>(y_tm1, s->amax);

    // 6. softmax + beta
    float* aw_out = out + (size_t)B_ * V_ + 2 * (size_t)B_ * D_;
    softmax_beta_kernel<<<B_, 256>>>(s->spart, s->h0, Wb, bb, ba2, aw_out, s->beta);

    // 7. context
    ctx_kernel<<<dim3(B_, E_ / 256), 256>>>(h, aw_out, s->beta, s->ctx);

    // 8. LSTM input + gates (two partial GEMMs; reduce folded into lstm kernel)
    xbuild_kernel<<<dim3(B_, WE_ / 256), 256>>>(emb, E_tm1, s->ctx, s->x);
    {
        SKJob2 jj;
        jj.j[0] = {s->x,  W_ih, WE_, WE_, 4 * D_, s->gp0};
        jj.j[1] = {s->h0, W_hh, D_,  D_,  4 * D_, s->gp1};
        sk_gemm_kernel<128><<<dim3(GN_4D, 2, 1), 256>>>(jj);
    }

    // 9. LSTM pointwise (+ gates reduce)
    lstm_kernel<<<dim3(B_, (D_ + 255) / 256), 256>>>(s->gp0, s->gp1, b_ih, b_hh, s->c0, out, s->z);

    // 10. z = [h_t, y_emb, ctx]
    zbuild_kernel<<<dim3(B_, WE_ / 256), 256>>>(emb, s->amax, s->ctx, s->z);

    // 11. logits
    {
        Job2 jj;
        jj.j[0] = {s->z, W_out, DWE_, DWE_, nullptr, nullptr, 0, 0, b_out, nullptr, out, V_};
        jj.j[1] = jj.j[0];
        mma_gemm_kernel<128, false><<<dim3(GN_V, 1), 256>>>(jj);
    }
}

// round 4
// speedup vs baseline: 3.8909x; 1.1970x over previous
#include <cuda_runtime.h>
#include <math.h>
#include <stdint.h>

#define S_ 196
#define B_ 64
#define E_ 1024
#define D_ 1800
#define W_ 512
#define V_ 32000
#define WE_ (W_ + E_)       // 1536
#define DE_ (D_ + E_)       // 2824
#define DWE_ (D_ + W_ + E_) // 3336

// ---------------------------------------------------------------------------
// Scratch
// ---------------------------------------------------------------------------
struct Scratch {
    float havg[B_ * E_];
    float skpA[2][3][B_ * D_];   // split-K partials, bank A
    float skpB[2][3][B_ * D_];   // split-K partials, bank B
    float qpart[B_ * D_];
    float spart[3 * S_ * B_];
    float beta[B_];
    float ctx[B_ * E_];
    float x[B_ * WE_];
    float z[B_ * DWE_];
    float gp0[B_ * 4 * D_];
    float gp1[B_ * 4 * D_];
    int   amax[B_];
};
__device__ Scratch g_s;

// ---------------------------------------------------------------------------
// tf32 helpers
// ---------------------------------------------------------------------------
__device__ __forceinline__ uint32_t f2tf32(float f) {
    uint32_t u;
    asm("cvt.rna.tf32.f32 %0, %1;" : "=r"(u) : "f"(f));
    return u;
}
__device__ __forceinline__ void mma_tf32(float (&c)[4], const uint32_t (&a)[4],
                                         const uint32_t b0, const uint32_t b1) {
    asm volatile(
        "mma.sync.aligned.m16n8k8.row.col.f32.tf32.tf32.f32 "
        "{%0,%1,%2,%3},{%4,%5,%6,%7},{%8,%9},{%0,%1,%2,%3};"
        : "+f"(c[0]), "+f"(c[1]), "+f"(c[2]), "+f"(c[3])
        : "r"(a[0]), "r"(a[1]), "r"(a[2]), "r"(a[3]), "r"(b0), "r"(b1));
}

__device__ __forceinline__ void ld8(float* d, const float* p) {
    float4 a = ((const float4*)p)[0], b = ((const float4*)p)[1];
    d[0]=a.x; d[1]=a.y; d[2]=a.z; d[3]=a.w; d[4]=b.x; d[5]=b.y; d[6]=b.z; d[7]=b.w;
}
__device__ __forceinline__ void add8(float* d, const float* p) {
    float4 a = ((const float4*)p)[0], b = ((const float4*)p)[1];
    d[0]+=a.x; d[1]+=a.y; d[2]+=a.z; d[3]+=a.w; d[4]+=b.x; d[5]+=b.y; d[6]+=b.z; d[7]+=b.w;
}

// SPAD = 20 uint2 (row stride): fragment-load lanes hit double-banks (4g+t) mod 16
// -> conflict-free LDS.64 for both A and B fragments.
#define SPAD 20

// ---------------------------------------------------------------------------
// Small-GEMM K-segment with fused A-side reduce (up to 3 partials + k-bias + relu).
// ---------------------------------------------------------------------------
struct SKJob {
    const float* A0; const float* A1p; const float* A2p;   // A partials (A1p/A2p nullable)
    const float* kb; int krelu;                            // per-k bias + relu of A
    const float* W; int K; int ldw; int N; float* Cpart;
};
struct SKJob2 { SKJob j[2]; };

template<int BN>
__device__ __forceinline__ void seg64(
    const SKJob& j, const int nb, const int t0, const int t1,
    uint2 As[64][SPAD], uint2 Ws[BN][SPAD],
    float (&acc)[2][BN / 32][4])
{
    constexpr int NF  = BN / 32;
    constexpr int WPT = (BN == 64) ? 8 : 16;
    const int tid  = threadIdx.x;
    const int lane = tid & 31, wid = tid >> 5;
    const int warpM = wid >> 2, warpN = wid & 3;
    const int g = lane >> 2, t = lane & 3;

    const int am  = tid & 63, akg = (tid >> 6) * 8;
    const int wn  = (BN == 64) ? (tid & 63) : (tid & 127);
    const int wkg = (BN == 64) ? ((tid >> 6) * 8) : ((tid >> 7) * 16);
    const bool wvalid = (nb + wn) < j.N;
    const int K = j.K;
    const float* A0r = j.A0 + (size_t)am * K;
    const float* A1r = j.A1p ? j.A1p + (size_t)am * K : nullptr;
    const float* A2r = j.A2p ? j.A2p + (size_t)am * K : nullptr;
    const float* Wbase = j.W + (size_t)(nb + wn) * j.ldw;

    float ra[8];
    float rw[WPT];

    auto loadA = [&](int ti) {
        const int k0 = ti * 32 + akg;
        if (k0 + 8 <= K) {
            ld8(ra, A0r + k0);
            if (A1r) add8(ra, A1r + k0);
            if (A2r) add8(ra, A2r + k0);
            if (j.kb) add8(ra, j.kb + k0);
        } else {
            #pragma unroll
            for (int i = 0; i < 8; i++) {
                int k = k0 + i; float v = 0.f;
                if (k < K) {
                    v = A0r[k];
                    if (A1r) v += A1r[k];
                    if (A2r) v += A2r[k];
                    if (j.kb) v += j.kb[k];
                }
                ra[i] = v;
            }
        }
        if (j.krelu) {
            #pragma unroll
            for (int i = 0; i < 8; i++) ra[i] = fmaxf(ra[i], 0.f);
        }
    };
    auto loadW = [&](int ti) {
        const int k0 = ti * 32 + wkg;
        if (wvalid && k0 + WPT <= K) {
            #pragma unroll
            for (int i = 0; i < WPT / 4; i++) {
                float4 v = *(const float4*)(Wbase + k0 + i * 4);
                rw[i*4+0]=v.x; rw[i*4+1]=v.y; rw[i*4+2]=v.z; rw[i*4+3]=v.w;
            }
        } else {
            #pragma unroll
            for (int i = 0; i < WPT; i++)
                rw[i] = (wvalid && (k0 + i) < K) ? Wbase[k0 + i] : 0.f;
        }
    };

    loadA(t0);
    loadW(t0);

    for (int ti = t0; ti < t1; ti++) {
        __syncthreads();
        {
            const int ks = akg >> 3;
            uint4* p = (uint4*)&As[am][ks * 4];
            p[0] = make_uint4(f2tf32(ra[0]), f2tf32(ra[4]), f2tf32(ra[1]), f2tf32(ra[5]));
            p[1] = make_uint4(f2tf32(ra[2]), f2tf32(ra[6]), f2tf32(ra[3]), f2tf32(ra[7]));
        }
        {
            #pragma unroll
            for (int h8 = 0; h8 < WPT / 8; h8++) {
                const int ks = (wkg >> 3) + h8;
                const float* r = rw + h8 * 8;
                uint4* p = (uint4*)&Ws[wn][ks * 4];
                p[0] = make_uint4(f2tf32(r[0]), f2tf32(r[4]), f2tf32(r[1]), f2tf32(r[5]));
                p[1] = make_uint4(f2tf32(r[2]), f2tf32(r[6]), f2tf32(r[3]), f2tf32(r[7]));
            }
        }
        __syncthreads();

        if (ti + 1 < t1) { loadA(ti + 1); loadW(ti + 1); }

        #pragma unroll
        for (int ks = 0; ks < 4; ks++) {
            uint32_t a[2][4];
            #pragma unroll
            for (int mf = 0; mf < 2; mf++) {
                const int r = warpM * 32 + mf * 16 + g;
                uint2 lo = As[r][ks * 4 + t];
                uint2 hi = As[r + 8][ks * 4 + t];
                a[mf][0] = lo.x; a[mf][1] = hi.x;
                a[mf][2] = lo.y; a[mf][3] = hi.y;
            }
            #pragma unroll
            for (int nf = 0; nf < NF; nf++) {
                const int n = warpN * (BN / 4) + nf * 8 + g;
                uint2 b = Ws[n][ks * 4 + t];
                #pragma unroll
                for (int mf = 0; mf < 2; mf++)
                    mma_tf32(acc[mf][nf], a[mf], b.x, b.y);
            }
        }
    }
}

// Split-K GEMM partials: grid (tiles, jobs, KS)
template<int BN>
__global__ __launch_bounds__(256) void sk_gemm_kernel(SKJob2 jobs)
{
    constexpr int NF = BN / 32;
    __shared__ uint2 As[64][SPAD];
    __shared__ uint2 Ws[BN][SPAD];

    const SKJob j = jobs.j[blockIdx.y];
    const int nb = blockIdx.x * BN;
    if (nb >= j.N) return;

    const int tiles = (j.K + 31) >> 5;
    const int KS = gridDim.z, kz = blockIdx.z;
    const int tpk = (tiles + KS - 1) / KS;
    const int t0 = kz * tpk;
    const int t1 = (t0 + tpk < tiles) ? (t0 + tpk) : tiles;

    float acc[2][NF][4] = {};
    if (t0 < t1)
        seg64<BN>(j, nb, t0, t1, As, Ws, acc);

    float* C = j.Cpart + (size_t)kz * 64 * j.N;
    const int tid = threadIdx.x, lane = tid & 31, wid = tid >> 5;
    const int warpM = wid >> 2, warpN = wid & 3;
    const int g = lane >> 2, t = lane & 3;

    #pragma unroll
    for (int mf = 0; mf < 2; mf++) {
        const int row = warpM * 32 + mf * 16 + g;
        #pragma unroll
        for (int nf = 0; nf < NF; nf++) {
            const int col = nb + warpN * (BN / 4) + nf * 8 + 2 * t;
            if (col < j.N) {
                *(float2*)&C[(size_t)row * j.N + col]       = make_float2(acc[mf][nf][0], acc[mf][nf][1]);
                *(float2*)&C[(size_t)(row + 8) * j.N + col] = make_float2(acc[mf][nf][2], acc[mf][nf][3]);
            }
        }
    }
}

// qpart reduce: 3 partials + bias
__global__ __launch_bounds__(256) void sk_reduce3_kernel(
    const float* __restrict__ part, const float* __restrict__ bias,
    float* __restrict__ outp)
{
    int idx = blockIdx.x * 256 + threadIdx.x;
    if (idx >= B_ * D_) return;
    int n = idx % D_;
    float v = bias[n] + part[idx] + part[(size_t)B_ * D_ + idx] + part[2 * (size_t)B_ * D_ + idx];
    outp[idx] = v;
}

// Logits: full GEMM + bias epilogue
__global__ __launch_bounds__(256) void logits_kernel(
    const float* __restrict__ z, const float* __restrict__ Wt,
    const float* __restrict__ bias, float* __restrict__ C)
{
    __shared__ uint2 As[64][SPAD];
    __shared__ uint2 Ws[128][SPAD];

    SKJob j; j.A0 = z; j.A1p = nullptr; j.A2p = nullptr; j.kb = nullptr; j.krelu = 0;
    j.W = Wt; j.K = DWE_; j.ldw = DWE_; j.N = V_; j.Cpart = nullptr;
    const int nb = blockIdx.x * 128;

    float acc[2][4][4] = {};
    seg64<128>(j, nb, 0, (DWE_ + 31) >> 5, As, Ws, acc);

    const int tid = threadIdx.x, lane = tid & 31, wid = tid >> 5;
    const int warpM = wid >> 2, warpN = wid & 3;
    const int g = lane >> 2, t = lane & 3;

    #pragma unroll
    for (int mf = 0; mf < 2; mf++) {
        const int row = warpM * 32 + mf * 16 + g;
        #pragma unroll
        for (int nf = 0; nf < 4; nf++) {
            const int col = nb + warpN * 32 + nf * 8 + 2 * t;
            float b0 = bias[col], b1 = bias[col + 1];
            *(float2*)&C[(size_t)row * V_ + col]       = make_float2(acc[mf][nf][0] + b0, acc[mf][nf][1] + b1);
            *(float2*)&C[(size_t)(row + 8) * V_ + col] = make_float2(acc[mf][nf][2] + b0, acc[mf][nf][3] + b1);
        }
    }
}

// ---------------------------------------------------------------------------
// Fused attention scores. BM=256 (4 seq), BN=128, warp tile 64x64 (4x2 warps),
// ktile=16, ping-pong smem (1 sync/iter), conflict-free [ks][t][row] layout.
// grid = (49, 3).
// ---------------------------------------------------------------------------
#define RSA 260   // 256 rows + pad (stride % 16 == 4)
#define RSW 132   // 128 cols + pad
#define SC_DYN ((size_t)(2*2*4*RSA + 2*2*4*RSW) * sizeof(uint2))

__global__ __launch_bounds__(256, 1) void mma_scores_kernel(
    const float* __restrict__ h, const float* __restrict__ Wa1h,
    const float* __restrict__ qpart, const float* __restrict__ Wa2,
    float* __restrict__ spart)
{
    extern __shared__ uint2 dynsm[];
    uint2 (*As)[2][4][RSA] = reinterpret_cast<uint2(*)[2][4][RSA]>(dynsm);
    uint2 (*Ws)[2][4][RSW] = reinterpret_cast<uint2(*)[2][4][RSW]>(dynsm + 2 * 2 * 4 * RSA);

    const int tid = threadIdx.x, lane = tid & 31, wid = tid >> 5;
    const int warpM = wid >> 1, warpN = wid & 1;
    const int g = lane >> 2, t = lane & 3;

    const int arow = tid;
    const float* Abase = h + ((size_t)blockIdx.x * 256 + arow) * E_;
    const int wrow = tid >> 1, wks = tid & 1;

    float sacc[4][2] = {};

    const int tile0 = blockIdx.y * 5;
    for (int tile = tile0; tile < tile0 + 5; tile++) {
        const int nb = tile * 128;
        const bool wv = (nb + wrow) < D_;
        const float* Wbase = Wa1h + (size_t)(nb + wrow) * DE_ + wks * 8;

        float ra[16], rw[8];
        float acc[4][8][4] = {};

        auto loadA = [&](int ti) {
            const float4* p = (const float4*)(Abase + ti * 16);
            float4 v0 = p[0], v1 = p[1], v2 = p[2], v3 = p[3];
            ra[0]=v0.x; ra[1]=v0.y; ra[2]=v0.z; ra[3]=v0.w;
            ra[4]=v1.x; ra[5]=v1.y; ra[6]=v1.z; ra[7]=v1.w;
            ra[8]=v2.x; ra[9]=v2.y; ra[10]=v2.z; ra[11]=v2.w;
            ra[12]=v3.x; ra[13]=v3.y; ra[14]=v3.z; ra[15]=v3.w;
        };
        auto loadW = [&](int ti) {
            if (wv) {
                const float4* p = (const float4*)(Wbase + ti * 16);
                float4 v0 = p[0], v1 = p[1];
                rw[0]=v0.x; rw[1]=v0.y; rw[2]=v0.z; rw[3]=v0.w;
                rw[4]=v1.x; rw[5]=v1.y; rw[6]=v1.z; rw[7]=v1.w;
            } else {
                #pragma unroll
                for (int i = 0; i < 8; i++) rw[i] = 0.f;
            }
        };
        auto stsAB = [&](int buf) {
            #pragma unroll
            for (int ks = 0; ks < 2; ks++)
                #pragma unroll
                for (int tt = 0; tt < 4; tt++)
                    As[buf][ks][tt][arow] =
                        make_uint2(f2tf32(ra[ks*8+tt]), f2tf32(ra[ks*8+tt+4]));
            #pragma unroll
            for (int tt = 0; tt < 4; tt++)
                Ws[buf][wks][tt][wrow] =
                    make_uint2(f2tf32(rw[tt]), f2tf32(rw[tt+4]));
        };
        auto domma = [&](int buf) {
            #pragma unroll
            for (int ks = 0; ks < 2; ks++) {
                uint32_t a[4][4];
                #pragma unroll
                for (int mf = 0; mf < 4; mf++) {
                    const int r = warpM * 64 + mf * 16 + g;
                    uint2 lo = As[buf][ks][t][r];
                    uint2 hi = As[buf][ks][t][r + 8];
                    a[mf][0] = lo.x; a[mf][1] = hi.x;
                    a[mf][2] = lo.y; a[mf][3] = hi.y;
                }
                #pragma unroll
                for (int nf = 0; nf < 8; nf++) {
                    const int c = warpN * 64 + nf * 8 + g;
                    uint2 b = Ws[buf][ks][t][c];
                    #pragma unroll
                    for (int mf = 0; mf < 4; mf++)
                        mma_tf32(acc[mf][nf], a[mf], b.x, b.y);
                }
            }
        };

        loadA(0); loadW(0);
        __syncthreads();
        stsAB(0);
        loadA(1); loadW(1);

        for (int ti = 0; ti < E_ / 16; ti++) {
            __syncthreads();
            if (ti + 1 < E_ / 16) stsAB((ti + 1) & 1);
            if (ti + 2 < E_ / 16) { loadA(ti + 2); loadW(ti + 2); }
            domma(ti & 1);
        }

        // epilogue: + qpart, relu, * Wa2, accumulate per-row
        #pragma unroll
        for (int mf = 0; mf < 4; mf++) {
            const int r0 = warpM * 64 + mf * 16 + g;
            const int b0 = r0 & 63, b1 = (r0 + 8) & 63;
            #pragma unroll
            for (int nf = 0; nf < 8; nf++) {
                const int col = nb + warpN * 64 + nf * 8 + 2 * t;
                if (col < D_) {
                    float2 w  = *(const float2*)(Wa2 + col);
                    float2 q0 = *(const float2*)(qpart + (size_t)b0 * D_ + col);
                    float2 q1 = *(const float2*)(qpart + (size_t)b1 * D_ + col);
                    sacc[mf][0] += fmaxf(acc[mf][nf][0] + q0.x, 0.f) * w.x
                                 + fmaxf(acc[mf][nf][1] + q0.y, 0.f) * w.y;
                    sacc[mf][1] += fmaxf(acc[mf][nf][2] + q1.x, 0.f) * w.x
                                 + fmaxf(acc[mf][nf][3] + q1.y, 0.f) * w.y;
                }
            }
        }
    }

    __syncthreads();
    float* red = (float*)dynsm;     // [256][9] overlay
    #pragma unroll
    for (int mf = 0; mf < 4; mf++) {
        const int r0 = warpM * 64 + mf * 16 + g;
        red[r0 * 9 + warpN * 4 + t]       = sacc[mf][0];
        red[(r0 + 8) * 9 + warpN * 4 + t] = sacc[mf][1];
    }
    __syncthreads();
    {
        const int row = tid;
        float a = 0.f;
        #pragma unroll
        for (int c = 0; c < 8; c++) a += red[row * 9 + c];
        const int s = blockIdx.x * 4 + (row >> 6);
        const int b = row & 63;
        spart[(size_t)blockIdx.y * S_ * B_ + (size_t)s * B_ + b] = a;
    }
}

// ---------------------------------------------------------------------------
// Small kernels
// ---------------------------------------------------------------------------
__global__ void havg_kernel(const float* __restrict__ h, float* __restrict__ havg)
{
    int b = blockIdx.x;
    int e = blockIdx.y * 256 + threadIdx.x;
    float s = 0.f;
    for (int si = 0; si < S_; si++)
        s += h[((size_t)si * B_ + b) * E_ + e];
    havg[(size_t)b * E_ + e] = s * (1.f / (float)S_);
}

__global__ __launch_bounds__(256) void softmax_beta_kernel(
    const float* __restrict__ spart,
    const float* __restrict__ hp0, const float* __restrict__ hp1,
    const float* __restrict__ hp2, const float* __restrict__ bh2,
    const float* __restrict__ Wb, const float* __restrict__ bb,
    const float* __restrict__ ba2,
    float* __restrict__ aw_out, float* __restrict__ beta)
{
    int b = blockIdx.x, tid = threadIdx.x;
    __shared__ float sm[256];

    float p = 0.f;
    for (int d = tid; d < D_; d += 256) {
        size_t i = (size_t)b * D_ + d;
        float hv = hp0[i] + hp1[i] + hp2[i] + bh2[d];
        p = fmaf(hv, Wb[d], p);
    }
    sm[tid] = p; __syncthreads();
    for (int o = 128; o > 0; o >>= 1) { if (tid < o) sm[tid] += sm[tid + o]; __syncthreads(); }
    if (tid == 0) beta[b] = 1.f / (1.f + expf(-(sm[0] + bb[0])));
    __syncthreads();

    float v = -3.4e38f;
    if (tid < S_) {
        size_t idx = (size_t)tid * B_ + b;
        v = spart[idx] + spart[(size_t)S_ * B_ + idx] + spart[2 * (size_t)S_ * B_ + idx] + ba2[0];
    }
    sm[tid] = v; __syncthreads();
    for (int o = 128; o > 0; o >>= 1) { if (tid < o) sm[tid] = fmaxf(sm[tid], sm[tid + o]); __syncthreads(); }
    float mx = sm[0]; __syncthreads();
    float e = (tid < S_) ? expf(v - mx) : 0.f;
    sm[tid] = e; __syncthreads();
    for (int o = 128; o > 0; o >>= 1) { if (tid < o) sm[tid] += sm[tid + o]; __syncthreads(); }
    float inv = 1.f / sm[0];
    if (tid < S_) aw_out[(size_t)tid * B_ + b] = e * inv;
}

__global__ void ctx_kernel(const float* __restrict__ h, const float* __restrict__ aw,
                           const float* __restrict__ beta, float* __restrict__ ctx)
{
    int b = blockIdx.x;
    int e = blockIdx.y * 256 + threadIdx.x;
    float s = 0.f;
    for (int si = 0; si < S_; si++)
        s = fmaf(aw[(size_t)si * B_ + b], h[((size_t)si * B_ + b) * E_ + e], s);
    ctx[(size_t)b * E_ + e] = s * beta[b];
}

__global__ __launch_bounds__(256) void argmax_kernel(const float* __restrict__ y, int* __restrict__ amax)
{
    int b = blockIdx.x, tid = threadIdx.x;
    float bm = -3.4e38f; int bi = 0;
    for (int i = tid; i < V_; i += 256) {
        float v = y[(size_t)b * V_ + i];
        if (v > bm) { bm = v; bi = i; }
    }
    __shared__ float sv[256];
    __shared__ int si_[256];
    sv[tid] = bm; si_[tid] = bi; __syncthreads();
    for (int o = 128; o > 0; o >>= 1) {
        if (tid < o) {
            if (sv[tid + o] > sv[tid] || (sv[tid + o] == sv[tid] && si_[tid + o] < si_[tid])) {
                sv[tid] = sv[tid + o]; si_[tid] = si_[tid + o];
            }
        }
        __syncthreads();
    }
    if (tid == 0) amax[b] = si_[0];
}

__global__ void xbuild_kernel(const float* __restrict__ emb, const int* __restrict__ Etm1,
                              const float* __restrict__ ctx, float* __restrict__ x)
{
    int b = blockIdx.x;
    int i = blockIdx.y * 256 + threadIdx.x;
    if (i < W_) x[(size_t)b * WE_ + i] = emb[(size_t)Etm1[b] * W_ + i];
    else        x[(size_t)b * WE_ + i] = ctx[(size_t)b * E_ + (i - W_)];
}

// LSTM pointwise; reduces gate partials + biases, and c0 from its partials.
__global__ void lstm_kernel(const float* __restrict__ gp0, const float* __restrict__ gp1,
                            const float* __restrict__ b_ih, const float* __restrict__ b_hh,
                            const float* __restrict__ cp0, const float* __restrict__ cp1,
                            const float* __restrict__ cp2, const float* __restrict__ bc2,
                            float* __restrict__ out, float* __restrict__ z)
{
    int b = blockIdx.x;
    int d = blockIdx.y * 256 + threadIdx.x;
    if (d >= D_) return;
    const size_t base = (size_t)b * 4 * D_;
    float gi = gp0[base + d]          + gp1[base + d]          + b_ih[d]          + b_hh[d];
    float gf = gp0[base + D_ + d]     + gp1[base + D_ + d]     + b_ih[D_ + d]     + b_hh[D_ + d];
    float gg = gp0[base + 2*D_ + d]   + gp1[base + 2*D_ + d]   + b_ih[2*D_ + d]   + b_hh[2*D_ + d];
    float go = gp0[base + 3*D_ + d]   + gp1[base + 3*D_ + d]   + b_ih[3*D_ + d]   + b_hh[3*D_ + d];
    size_t ci = (size_t)b * D_ + d;
    float c0 = cp0[ci] + cp1[ci] + cp2[ci] + bc2[d];
    float ig = 1.f / (1.f + expf(-gi));
    float fg = 1.f / (1.f + expf(-gf));
    float gt = tanhf(gg);
    float og = 1.f / (1.f + expf(-go));
    float c = fmaf(fg, c0, ig * gt);
    float ht = og * tanhf(c);
    out[(size_t)B_ * V_ + (size_t)b * D_ + d] = ht;
    out[(size_t)B_ * V_ + (size_t)B_ * D_ + (size_t)b * D_ + d] = c;
    z[(size_t)b * DWE_ + d] = ht;
}

__global__ void zbuild_kernel(const float* __restrict__ emb, const int* __restrict__ amax,
                              const float* __restrict__ ctx, float* __restrict__ z)
{
    int b = blockIdx.x;
    int i = blockIdx.y * 256 + threadIdx.x;
    if (i < W_) z[(size_t)b * DWE_ + D_ + i] = emb[(size_t)amax[b] * W_ + i];
    else        z[(size_t)b * DWE_ + D_ + i] = ctx[(size_t)b * E_ + (i - W_)];
}

// ---------------------------------------------------------------------------
// Launch
// ---------------------------------------------------------------------------
extern "C" void kernel_launch(void* const* d_in, const int* in_sizes, int n_in,
                              void* d_out, int out_size)
{
    const int*   E_tm1 = (const int*)d_in[0];
    const float* y_tm1 = (const float*)d_in[1];
    const float* h     = (const float*)d_in[2];
    const float* emb   = (const float*)d_in[3];
    const float* W_ih  = (const float*)d_in[4];
    const float* b_ih  = (const float*)d_in[5];
    const float* W_hh  = (const float*)d_in[6];
    const float* b_hh  = (const float*)d_in[7];
    const float* W_out = (const float*)d_in[8];
    const float* b_out = (const float*)d_in[9];
    const float* Wh1 = (const float*)d_in[10]; const float* bh1 = (const float*)d_in[11];
    const float* Wh2 = (const float*)d_in[12]; const float* bh2 = (const float*)d_in[13];
    const float* Wc1 = (const float*)d_in[14]; const float* bc1 = (const float*)d_in[15];
    const float* Wc2 = (const float*)d_in[16]; const float* bc2 = (const float*)d_in[17];
    const float* Wa1 = (const float*)d_in[18]; const float* ba1 = (const float*)d_in[19];
    const float* Wa2 = (const float*)d_in[20]; const float* ba2 = (const float*)d_in[21];
    const float* Wb  = (const float*)d_in[22]; const float* bb  = (const float*)d_in[23];
    float* out = (float*)d_out;

    Scratch* s = nullptr;
    cudaGetSymbolAddress((void**)&s, g_s);

    cudaFuncSetAttribute(mma_scores_kernel,
                         cudaFuncAttributeMaxDynamicSharedMemorySize, (int)SC_DYN);

    const int GN_D  = (D_ + 63) / 64;            // 29
    const int GN_4D = (4 * D_ + 127) / 128;      // 57
    const int GN_V  = V_ / 128;                  // 250

    // 1. encoder mean
    havg_kernel<<<dim3(B_, E_ / 256), 256>>>(h, s->havg);

    // 2. init-state layer1 -> partials (KS=2)
    {
        SKJob2 jj;
        jj.j[0] = {s->havg, nullptr, nullptr, nullptr, 0, Wh1, E_, E_, D_, s->skpA[0][0]};
        jj.j[1] = {s->havg, nullptr, nullptr, nullptr, 0, Wc1, E_, E_, D_, s->skpA[1][0]};
        sk_gemm_kernel<64><<<dim3(GN_D, 2, 2), 256>>>(jj);
    }
    // 3. layer2, A = relu(sum L1 partials + b1) fused (KS=3)
    {
        SKJob2 jj;
        jj.j[0] = {s->skpA[0][0], s->skpA[0][1], nullptr, bh1, 1, Wh2, D_, D_, D_, s->skpB[0][0]};
        jj.j[1] = {s->skpA[1][0], s->skpA[1][1], nullptr, bc1, 1, Wc2, D_, D_, D_, s->skpB[1][0]};
        sk_gemm_kernel<64><<<dim3(GN_D, 2, 3), 256>>>(jj);
    }
    // 4. qpart = (h0 = sum L2 partials + bh2) @ Wa1[:, :D]^T  (KS=3)
    {
        SKJob2 jj;
        jj.j[0] = {s->skpB[0][0], s->skpB[0][1], s->skpB[0][2], bh2, 0, Wa1, D_, DE_, D_, s->skpA[0][0]};
        jj.j[1] = jj.j[0];
        sk_gemm_kernel<64><<<dim3(GN_D, 1, 3), 256>>>(jj);
    }
    // 5. qpart reduce (+ ba1)
    sk_reduce3_kernel<<<(B_ * D_ + 255) / 256, 256>>>(s->skpA[0][0], ba1, s->qpart);

    // 6. fused scores GEMM
    mma_scores_kernel<<<dim3(S_ / 4, 3), 256, SC_DYN>>>(h, Wa1 + D_, s->qpart, Wa2, s->spart);

    // 7. argmax of y_tm1
    argmax_kernel<<<B_, 256>>>(y_tm1, s->amax);

    // 8. softmax + beta (h0 virtual from partials)
    float* aw_out = out + (size_t)B_ * V_ + 2 * (size_t)B_ * D_;
    softmax_beta_kernel<<<B_, 256>>>(s->spart, s->skpB[0][0], s->skpB[0][1], s->skpB[0][2],
                                     bh2, Wb, bb, ba2, aw_out, s->beta);

    // 9. context
    ctx_kernel<<<dim3(B_, E_ / 256), 256>>>(h, aw_out, s->beta, s->ctx);

    // 10. LSTM input + gates (h0 virtual in job1)
    xbuild_kernel<<<dim3(B_, WE_ / 256), 256>>>(emb, E_tm1, s->ctx, s->x);
    {
        SKJob2 jj;
        jj.j[0] = {s->x, nullptr, nullptr, nullptr, 0, W_ih, WE_, WE_, 4 * D_, s->gp0};
        jj.j[1] = {s->skpB[0][0], s->skpB[0][1], s->skpB[0][2], bh2, 0, W_hh, D_, D_, 4 * D_, s->gp1};
        sk_gemm_kernel<128><<<dim3(GN_4D, 2, 1), 256>>>(jj);
    }

    // 11. LSTM pointwise (c0 virtual from partials)
    lstm_kernel<<<dim3(B_, (D_ + 255) / 256), 256>>>(
        s->gp0, s->gp1, b_ih, b_hh,
        s->skpB[1][0], s->skpB[1][1], s->skpB[1][2], bc2, out, s->z);

    // 12. z tail
    zbuild_kernel<<<dim3(B_, WE_ / 256), 256>>>(emb, s->amax, s->ctx, s->z);

    // 13. logits
    logits_kernel<<<GN_V, 256>>>(s->z, W_out, b_out, out);
}

// round 8
// speedup vs baseline: 5.3328x; 1.3706x over previous
#include <cuda_runtime.h>
#include <cuda_fp16.h>
#include <math.h>
#include <stdint.h>

#define S_ 196
#define B_ 64
#define E_ 1024
#define D_ 1800
#define W_ 512
#define V_ 32000
#define WE_ (W_ + E_)       // 1536
#define DE_ (D_ + E_)       // 2824
#define DWE_ (D_ + W_ + E_) // 3336

// ---------------------------------------------------------------------------
// Scratch
// ---------------------------------------------------------------------------
struct Scratch {
    float havg[B_ * E_];
    float skpA[2][3][B_ * D_];
    float skpB[2][3][B_ * D_];
    float qpart[B_ * D_];
    float spart[3 * S_ * B_];
    float beta[B_];
    float ctx[B_ * E_];
    float x[B_ * WE_];
    float z[B_ * DWE_];
    float gp0[B_ * 4 * D_];
    float gp1[B_ * 4 * D_];
    int   amax[B_];
};
__device__ Scratch g_s;

// ---------------------------------------------------------------------------
// fp16 MMA helpers
// ---------------------------------------------------------------------------
__device__ __forceinline__ uint32_t packh2(float a, float b) {
    __half2 h = __floats2half2_rn(a, b);
    return *(uint32_t*)&h;
}
__device__ __forceinline__ void mma_f16(float (&c)[4], const uint32_t (&a)[4],
                                        const uint32_t b0, const uint32_t b1) {
    asm volatile(
        "mma.sync.aligned.m16n8k16.row.col.f32.f16.f16.f32 "
        "{%0,%1,%2,%3},{%4,%5,%6,%7},{%8,%9},{%0,%1,%2,%3};"
        : "+f"(c[0]), "+f"(c[1]), "+f"(c[2]), "+f"(c[3])
        : "r"(a[0]), "r"(a[1]), "r"(a[2]), "r"(a[3]), "r"(b0), "r"(b1));
}
__device__ __forceinline__ void ldsm4(uint32_t (&r)[4], uint32_t addr) {
    asm volatile("ldmatrix.sync.aligned.m8n8.x4.shared.b16 {%0,%1,%2,%3}, [%4];"
        : "=r"(r[0]), "=r"(r[1]), "=r"(r[2]), "=r"(r[3]) : "r"(addr));
}
__device__ __forceinline__ void ldsm2(uint32_t (&r)[2], uint32_t addr) {
    asm volatile("ldmatrix.sync.aligned.m8n8.x2.shared.b16 {%0,%1}, [%2];"
        : "=r"(r[0]), "=r"(r[1]) : "r"(addr));
}
__device__ __forceinline__ void ld8(float* d, const float* p) {
    float4 a = ((const float4*)p)[0], b = ((const float4*)p)[1];
    d[0]=a.x; d[1]=a.y; d[2]=a.z; d[3]=a.w; d[4]=b.x; d[5]=b.y; d[6]=b.z; d[7]=b.w;
}
__device__ __forceinline__ void add8(float* d, const float* p) {
    float4 a = ((const float4*)p)[0], b = ((const float4*)p)[1];
    d[0]+=a.x; d[1]+=a.y; d[2]+=a.z; d[3]+=a.w; d[4]+=b.x; d[5]+=b.y; d[6]+=b.z; d[7]+=b.w;
}

// Row stride for k-tile 32 (16 half2 pairs + 4 pad): bases r*20 mod 32 are
// {0,20,8,28,16,4,24,12} -> conflict-free LDSM row fetches.
#define SPADH 20

// ---------------------------------------------------------------------------
// Small-GEMM K-segment, fp16 MMA, fused A-side reduce (partials + k-bias + relu)
// ---------------------------------------------------------------------------
struct SKJob {
    const float* A0; const float* A1p; const float* A2p;
    const float* kb; int krelu;
    const float* W; int K; int ldw; int N; float* Cpart;
};
struct SKJob2 { SKJob j[2]; };

template<int BN>
__device__ __forceinline__ void seg64(
    const SKJob& j, const int nb, const int t0, const int t1,
    uint32_t As[64][SPADH], uint32_t Ws[BN][SPADH],
    float (&acc)[2][BN / 32][4])
{
    constexpr int NF  = BN / 32;
    constexpr int WPT = (BN == 64) ? 8 : 16;
    const int tid  = threadIdx.x;
    const int lane = tid & 31, wid = tid >> 5;
    const int warpM = wid >> 2, warpN = wid & 3;

    const int am  = tid & 63, akg = (tid >> 6) * 8;
    const int wn  = (BN == 64) ? (tid & 63) : (tid & 127);
    const int wkg = (BN == 64) ? ((tid >> 6) * 8) : ((tid >> 7) * 16);
    const bool wvalid = (nb + wn) < j.N;
    const int K = j.K;
    const float* A0r = j.A0 + (size_t)am * K;
    const float* A1r = j.A1p ? j.A1p + (size_t)am * K : nullptr;
    const float* A2r = j.A2p ? j.A2p + (size_t)am * K : nullptr;
    const float* Wbase = j.W + (size_t)(nb + wn) * j.ldw;

    // ldmatrix lane addresses
    uint32_t aAddr[2][2], bAddr[NF];
    #pragma unroll
    for (int mf = 0; mf < 2; mf++)
        #pragma unroll
        for (int ks = 0; ks < 2; ks++)
            aAddr[mf][ks] = (uint32_t)__cvta_generic_to_shared(
                &As[warpM * 32 + mf * 16 + (lane & 15)][ks * 8 + 4 * (lane >> 4)]);
    #pragma unroll
    for (int nf = 0; nf < NF; nf++)
        bAddr[nf] = (uint32_t)__cvta_generic_to_shared(
            &Ws[warpN * (BN / 4) + nf * 8 + (lane & 7)][4 * (lane >> 3)]);

    float ra[8], rw[WPT];

    auto loadA = [&](int ti) {
        const int k0 = ti * 32 + akg;
        if (k0 + 8 <= K) {
            ld8(ra, A0r + k0);
            if (A1r) add8(ra, A1r + k0);
            if (A2r) add8(ra, A2r + k0);
            if (j.kb) add8(ra, j.kb + k0);
        } else {
            #pragma unroll
            for (int i = 0; i < 8; i++) {
                int k = k0 + i; float v = 0.f;
                if (k < K) {
                    v = A0r[k];
                    if (A1r) v += A1r[k];
                    if (A2r) v += A2r[k];
                    if (j.kb) v += j.kb[k];
                }
                ra[i] = v;
            }
        }
        if (j.krelu) {
            #pragma unroll
            for (int i = 0; i < 8; i++) ra[i] = fmaxf(ra[i], 0.f);
        }
    };
    auto loadW = [&](int ti) {
        const int k0 = ti * 32 + wkg;
        if (wvalid && k0 + WPT <= K) {
            #pragma unroll
            for (int i = 0; i < WPT / 4; i++) {
                float4 v = *(const float4*)(Wbase + k0 + i * 4);
                rw[i*4+0]=v.x; rw[i*4+1]=v.y; rw[i*4+2]=v.z; rw[i*4+3]=v.w;
            }
        } else {
            #pragma unroll
            for (int i = 0; i < WPT; i++)
                rw[i] = (wvalid && (k0 + i) < K) ? Wbase[k0 + i] : 0.f;
        }
    };

    loadA(t0);
    loadW(t0);

    for (int ti = t0; ti < t1; ti++) {
        __syncthreads();
        *(uint4*)&As[am][akg >> 1] =
            make_uint4(packh2(ra[0], ra[1]), packh2(ra[2], ra[3]),
                       packh2(ra[4], ra[5]), packh2(ra[6], ra[7]));
        #pragma unroll
        for (int h8 = 0; h8 < WPT / 8; h8++) {
            const float* r = rw + h8 * 8;
            *(uint4*)&Ws[wn][(wkg >> 1) + h8 * 4] =
                make_uint4(packh2(r[0], r[1]), packh2(r[2], r[3]),
                           packh2(r[4], r[5]), packh2(r[6], r[7]));
        }
        __syncthreads();

        if (ti + 1 < t1) { loadA(ti + 1); loadW(ti + 1); }

        uint32_t b[NF][4];
        #pragma unroll
        for (int nf = 0; nf < NF; nf++) ldsm4(b[nf], bAddr[nf]);
        #pragma unroll
        for (int ks = 0; ks < 2; ks++) {
            uint32_t a[2][4];
            ldsm4(a[0], aAddr[0][ks]);
            ldsm4(a[1], aAddr[1][ks]);
            #pragma unroll
            for (int nf = 0; nf < NF; nf++) {
                mma_f16(acc[0][nf], a[0], b[nf][2 * ks], b[nf][2 * ks + 1]);
                mma_f16(acc[1][nf], a[1], b[nf][2 * ks], b[nf][2 * ks + 1]);
            }
        }
    }
}

template<int BN>
__global__ __launch_bounds__(256) void sk_gemm_kernel(SKJob2 jobs)
{
    constexpr int NF = BN / 32;
    __shared__ __align__(16) uint32_t As[64][SPADH];
    __shared__ __align__(16) uint32_t Ws[BN][SPADH];

    const SKJob j = jobs.j[blockIdx.y];
    const int nb = blockIdx.x * BN;
    if (nb >= j.N) return;

    const int tiles = (j.K + 31) >> 5;
    const int KS = gridDim.z, kz = blockIdx.z;
    const int tpk = (tiles + KS - 1) / KS;
    const int t0 = kz * tpk;
    const int t1 = (t0 + tpk < tiles) ? (t0 + tpk) : tiles;

    float acc[2][NF][4] = {};
    if (t0 < t1)
        seg64<BN>(j, nb, t0, t1, As, Ws, acc);

    float* C = j.Cpart + (size_t)kz * 64 * j.N;
    const int tid = threadIdx.x, lane = tid & 31, wid = tid >> 5;
    const int warpM = wid >> 2, warpN = wid & 3;
    const int g = lane >> 2, t = lane & 3;

    #pragma unroll
    for (int mf = 0; mf < 2; mf++) {
        const int row = warpM * 32 + mf * 16 + g;
        #pragma unroll
        for (int nf = 0; nf < NF; nf++) {
            const int col = nb + warpN * (BN / 4) + nf * 8 + 2 * t;
            if (col < j.N) {
                *(float2*)&C[(size_t)row * j.N + col]       = make_float2(acc[mf][nf][0], acc[mf][nf][1]);
                *(float2*)&C[(size_t)(row + 8) * j.N + col] = make_float2(acc[mf][nf][2], acc[mf][nf][3]);
            }
        }
    }
}

__global__ __launch_bounds__(256) void sk_reduce3_kernel(
    const float* __restrict__ part, const float* __restrict__ bias,
    float* __restrict__ outp)
{
    int idx = blockIdx.x * 256 + threadIdx.x;
    if (idx >= B_ * D_) return;
    int n = idx % D_;
    float v = bias[n] + part[idx] + part[(size_t)B_ * D_ + idx] + part[2 * (size_t)B_ * D_ + idx];
    outp[idx] = v;
}

__global__ __launch_bounds__(256) void logits_kernel(
    const float* __restrict__ z, const float* __restrict__ Wt,
    const float* __restrict__ bias, float* __restrict__ C)
{
    __shared__ __align__(16) uint32_t As[64][SPADH];
    __shared__ __align__(16) uint32_t Ws[128][SPADH];

    SKJob j; j.A0 = z; j.A1p = nullptr; j.A2p = nullptr; j.kb = nullptr; j.krelu = 0;
    j.W = Wt; j.K = DWE_; j.ldw = DWE_; j.N = V_; j.Cpart = nullptr;
    const int nb = blockIdx.x * 128;

    float acc[2][4][4] = {};
    seg64<128>(j, nb, 0, (DWE_ + 31) >> 5, As, Ws, acc);

    const int tid = threadIdx.x, lane = tid & 31, wid = tid >> 5;
    const int warpM = wid >> 2, warpN = wid & 3;
    const int g = lane >> 2, t = lane & 3;

    #pragma unroll
    for (int mf = 0; mf < 2; mf++) {
        const int row = warpM * 32 + mf * 16 + g;
        #pragma unroll
        for (int nf = 0; nf < 4; nf++) {
            const int col = nb + warpN * 32 + nf * 8 + 2 * t;
            float b0 = bias[col], b1 = bias[col + 1];
            *(float2*)&C[(size_t)row * V_ + col]       = make_float2(acc[mf][nf][0] + b0, acc[mf][nf][1] + b1);
            *(float2*)&C[(size_t)(row + 8) * V_ + col] = make_float2(acc[mf][nf][2] + b0, acc[mf][nf][3] + b1);
        }
    }
}

// ---------------------------------------------------------------------------
// Fused attention scores, fp16 MMA. BM=256 (4 seq), BN=128, warp tile 64x64
// (4x2 warps), ktile=16 (1 k16 step), ping-pong smem (1 sync/iter).
// grid = (49, 3).
// ---------------------------------------------------------------------------
#define SPH 12   // 8 pairs + 4 pad; bases r*12 mod 32 distinct

__global__ __launch_bounds__(256, 1) void mma_scores_kernel(
    const float* __restrict__ h, const float* __restrict__ Wa1h,
    const float* __restrict__ qpart, const float* __restrict__ Wa2,
    float* __restrict__ spart)
{
    __shared__ __align__(16) uint32_t As[2][256][SPH];
    __shared__ __align__(16) uint32_t Ws[2][128][SPH];
    __shared__ float red[256][9];

    const int tid = threadIdx.x, lane = tid & 31, wid = tid >> 5;
    const int warpM = wid >> 1, warpN = wid & 1;
    const int g = lane >> 2, t = lane & 3;

    const int arow = tid;
    const float* Abase = h + ((size_t)blockIdx.x * 256 + arow) * E_;
    const int wrow = tid >> 1;
    const int wkh  = (tid & 1) * 8;    // k offset (8 floats per half-row)

    // ldmatrix addresses (buf 0; buf 1 adds a constant stride)
    const uint32_t AS_STRIDE = 256 * SPH * 4;
    const uint32_t WS_STRIDE = 128 * SPH * 4;
    uint32_t aA[4], bA[8];
    #pragma unroll
    for (int mf = 0; mf < 4; mf++)
        aA[mf] = (uint32_t)__cvta_generic_to_shared(
            &As[0][warpM * 64 + mf * 16 + (lane & 15)][4 * (lane >> 4)]);
    #pragma unroll
    for (int nf = 0; nf < 8; nf++)
        bA[nf] = (uint32_t)__cvta_generic_to_shared(
            &Ws[0][warpN * 64 + nf * 8 + (lane & 7)][4 * ((lane >> 3) & 1)]);

    float sacc[4][2] = {};

    const int tile0 = blockIdx.y * 5;
    for (int tile = tile0; tile < tile0 + 5; tile++) {
        const int nb = tile * 128;
        const bool wv = (nb + wrow) < D_;
        const float* Wbase = Wa1h + (size_t)(nb + wrow) * DE_ + wkh;

        float ra[16], rw[8];
        float acc[4][8][4] = {};

        auto loadA = [&](int ti) {
            const float4* p = (const float4*)(Abase + ti * 16);
            float4 v0 = p[0], v1 = p[1], v2 = p[2], v3 = p[3];
            ra[0]=v0.x; ra[1]=v0.y; ra[2]=v0.z; ra[3]=v0.w;
            ra[4]=v1.x; ra[5]=v1.y; ra[6]=v1.z; ra[7]=v1.w;
            ra[8]=v2.x; ra[9]=v2.y; ra[10]=v2.z; ra[11]=v2.w;
            ra[12]=v3.x; ra[13]=v3.y; ra[14]=v3.z; ra[15]=v3.w;
        };
        auto loadW = [&](int ti) {
            if (wv) {
                const float4* p = (const float4*)(Wbase + ti * 16);
                float4 v0 = p[0], v1 = p[1];
                rw[0]=v0.x; rw[1]=v0.y; rw[2]=v0.z; rw[3]=v0.w;
                rw[4]=v1.x; rw[5]=v1.y; rw[6]=v1.z; rw[7]=v1.w;
            } else {
                #pragma unroll
                for (int i = 0; i < 8; i++) rw[i] = 0.f;
            }
        };
        auto stsAB = [&](int buf) {
            *(uint4*)&As[buf][arow][0] =
                make_uint4(packh2(ra[0], ra[1]), packh2(ra[2], ra[3]),
                           packh2(ra[4], ra[5]), packh2(ra[6], ra[7]));
            *(uint4*)&As[buf][arow][4] =
                make_uint4(packh2(ra[8], ra[9]), packh2(ra[10], ra[11]),
                           packh2(ra[12], ra[13]), packh2(ra[14], ra[15]));
            *(uint4*)&Ws[buf][wrow][(tid & 1) * 4] =
                make_uint4(packh2(rw[0], rw[1]), packh2(rw[2], rw[3]),
                           packh2(rw[4], rw[5]), packh2(rw[6], rw[7]));
        };
        auto domma = [&](int buf) {
            const uint32_t ao = buf * AS_STRIDE, wo = buf * WS_STRIDE;
            uint32_t b[8][2];
            #pragma unroll
            for (int nf = 0; nf < 8; nf++) ldsm2(b[nf], bA[nf] + wo);
            #pragma unroll
            for (int mf = 0; mf < 4; mf++) {
                uint32_t a[4];
                ldsm4(a, aA[mf] + ao);
                #pragma unroll
                for (int nf = 0; nf < 8; nf++)
                    mma_f16(acc[mf][nf], a, b[nf][0], b[nf][1]);
            }
        };

        loadA(0); loadW(0);
        __syncthreads();
        stsAB(0);
        loadA(1); loadW(1);

        for (int ti = 0; ti < E_ / 16; ti++) {
            __syncthreads();
            if (ti + 1 < E_ / 16) stsAB((ti + 1) & 1);
            if (ti + 2 < E_ / 16) { loadA(ti + 2); loadW(ti + 2); }
            domma(ti & 1);
        }

        // epilogue: + qpart, relu, * Wa2, accumulate per-row
        #pragma unroll
        for (int mf = 0; mf < 4; mf++) {
            const int r0 = warpM * 64 + mf * 16 + g;
            const int b0 = r0 & 63, b1 = (r0 + 8) & 63;
            #pragma unroll
            for (int nf = 0; nf < 8; nf++) {
                const int col = nb + warpN * 64 + nf * 8 + 2 * t;
                if (col < D_) {
                    float2 w  = *(const float2*)(Wa2 + col);
                    float2 q0 = *(const float2*)(qpart + (size_t)b0 * D_ + col);
                    float2 q1 = *(const float2*)(qpart + (size_t)b1 * D_ + col);
                    sacc[mf][0] += fmaxf(acc[mf][nf][0] + q0.x, 0.f) * w.x
                                 + fmaxf(acc[mf][nf][1] + q0.y, 0.f) * w.y;
                    sacc[mf][1] += fmaxf(acc[mf][nf][2] + q1.x, 0.f) * w.x
                                 + fmaxf(acc[mf][nf][3] + q1.y, 0.f) * w.y;
                }
            }
        }
    }

    __syncthreads();
    #pragma unroll
    for (int mf = 0; mf < 4; mf++) {
        const int r0 = warpM * 64 + mf * 16 + g;
        red[r0][warpN * 4 + t]     = sacc[mf][0];
        red[r0 + 8][warpN * 4 + t] = sacc[mf][1];
    }
    __syncthreads();
    {
        const int row = tid;
        float a = 0.f;
        #pragma unroll
        for (int c = 0; c < 8; c++) a += red[row][c];
        const int s = blockIdx.x * 4 + (row >> 6);
        const int b = row & 63;
        spart[(size_t)blockIdx.y * S_ * B_ + (size_t)s * B_ + b] = a;
    }
}

// ---------------------------------------------------------------------------
// Small kernels (unchanged)
// ---------------------------------------------------------------------------
__global__ void havg_kernel(const float* __restrict__ h, float* __restrict__ havg)
{
    int b = blockIdx.x;
    int e = blockIdx.y * 256 + threadIdx.x;
    float s = 0.f;
    for (int si = 0; si < S_; si++)
        s += h[((size_t)si * B_ + b) * E_ + e];
    havg[(size_t)b * E_ + e] = s * (1.f / (float)S_);
}

__global__ __launch_bounds__(256) void softmax_beta_kernel(
    const float* __restrict__ spart,
    const float* __restrict__ hp0, const float* __restrict__ hp1,
    const float* __restrict__ hp2, const float* __restrict__ bh2,
    const float* __restrict__ Wb, const float* __restrict__ bb,
    const float* __restrict__ ba2,
    float* __restrict__ aw_out, float* __restrict__ beta)
{
    int b = blockIdx.x, tid = threadIdx.x;
    __shared__ float sm[256];

    float p = 0.f;
    for (int d = tid; d < D_; d += 256) {
        size_t i = (size_t)b * D_ + d;
        float hv = hp0[i] + hp1[i] + hp2[i] + bh2[d];
        p = fmaf(hv, Wb[d], p);
    }
    sm[tid] = p; __syncthreads();
    for (int o = 128; o > 0; o >>= 1) { if (tid < o) sm[tid] += sm[tid + o]; __syncthreads(); }
    if (tid == 0) beta[b] = 1.f / (1.f + expf(-(sm[0] + bb[0])));
    __syncthreads();

    float v = -3.4e38f;
    if (tid < S_) {
        size_t idx = (size_t)tid * B_ + b;
        v = spart[idx] + spart[(size_t)S_ * B_ + idx] + spart[2 * (size_t)S_ * B_ + idx] + ba2[0];
    }
    sm[tid] = v; __syncthreads();
    for (int o = 128; o > 0; o >>= 1) { if (tid < o) sm[tid] = fmaxf(sm[tid], sm[tid + o]); __syncthreads(); }
    float mx = sm[0]; __syncthreads();
    float e = (tid < S_) ? expf(v - mx) : 0.f;
    sm[tid] = e; __syncthreads();
    for (int o = 128; o > 0; o >>= 1) { if (tid < o) sm[tid] += sm[tid + o]; __syncthreads(); }
    float inv = 1.f / sm[0];
    if (tid < S_) aw_out[(size_t)tid * B_ + b] = e * inv;
}

__global__ void ctx_kernel(const float* __restrict__ h, const float* __restrict__ aw,
                           const float* __restrict__ beta, float* __restrict__ ctx)
{
    int b = blockIdx.x;
    int e = blockIdx.y * 256 + threadIdx.x;
    float s = 0.f;
    for (int si = 0; si < S_; si++)
        s = fmaf(aw[(size_t)si * B_ + b], h[((size_t)si * B_ + b) * E_ + e], s);
    ctx[(size_t)b * E_ + e] = s * beta[b];
}

__global__ __launch_bounds__(256) void argmax_kernel(const float* __restrict__ y, int* __restrict__ amax)
{
    int b = blockIdx.x, tid = threadIdx.x;
    float bm = -3.4e38f; int bi = 0;
    for (int i = tid; i < V_; i += 256) {
        float v = y[(size_t)b * V_ + i];
        if (v > bm) { bm = v; bi = i; }
    }
    __shared__ float sv[256];
    __shared__ int si_[256];
    sv[tid] = bm; si_[tid] = bi; __syncthreads();
    for (int o = 128; o > 0; o >>= 1) {
        if (tid < o) {
            if (sv[tid + o] > sv[tid] || (sv[tid + o] == sv[tid] && si_[tid + o] < si_[tid])) {
                sv[tid] = sv[tid + o]; si_[tid] = si_[tid + o];
            }
        }
        __syncthreads();
    }
    if (tid == 0) amax[b] = si_[0];
}

__global__ void xbuild_kernel(const float* __restrict__ emb, const int* __restrict__ Etm1,
                              const float* __restrict__ ctx, float* __restrict__ x)
{
    int b = blockIdx.x;
    int i = blockIdx.y * 256 + threadIdx.x;
    if (i < W_) x[(size_t)b * WE_ + i] = emb[(size_t)Etm1[b] * W_ + i];
    else        x[(size_t)b * WE_ + i] = ctx[(size_t)b * E_ + (i - W_)];
}

__global__ void lstm_kernel(const float* __restrict__ gp0, const float* __restrict__ gp1,
                            const float* __restrict__ b_ih, const float* __restrict__ b_hh,
                            const float* __restrict__ cp0, const float* __restrict__ cp1,
                            const float* __restrict__ cp2, const float* __restrict__ bc2,
                            float* __restrict__ out, float* __restrict__ z)
{
    int b = blockIdx.x;
    int d = blockIdx.y * 256 + threadIdx.x;
    if (d >= D_) return;
    const size_t base = (size_t)b * 4 * D_;
    float gi = gp0[base + d]          + gp1[base + d]          + b_ih[d]          + b_hh[d];
    float gf = gp0[base + D_ + d]     + gp1[base + D_ + d]     + b_ih[D_ + d]     + b_hh[D_ + d];
    float gg = gp0[base + 2*D_ + d]   + gp1[base + 2*D_ + d]   + b_ih[2*D_ + d]   + b_hh[2*D_ + d];
    float go = gp0[base + 3*D_ + d]   + gp1[base + 3*D_ + d]   + b_ih[3*D_ + d]   + b_hh[3*D_ + d];
    size_t ci = (size_t)b * D_ + d;
    float c0 = cp0[ci] + cp1[ci] + cp2[ci] + bc2[d];
    float ig = 1.f / (1.f + expf(-gi));
    float fg = 1.f / (1.f + expf(-gf));
    float gt = tanhf(gg);
    float og = 1.f / (1.f + expf(-go));
    float c = fmaf(fg, c0, ig * gt);
    float ht = og * tanhf(c);
    out[(size_t)B_ * V_ + (size_t)b * D_ + d] = ht;
    out[(size_t)B_ * V_ + (size_t)B_ * D_ + (size_t)b * D_ + d] = c;
    z[(size_t)b * DWE_ + d] = ht;
}

__global__ void zbuild_kernel(const float* __restrict__ emb, const int* __restrict__ amax,
                              const float* __restrict__ ctx, float* __restrict__ z)
{
    int b = blockIdx.x;
    int i = blockIdx.y * 256 + threadIdx.x;
    if (i < W_) z[(size_t)b * DWE_ + D_ + i] = emb[(size_t)amax[b] * W_ + i];
    else        z[(size_t)b * DWE_ + D_ + i] = ctx[(size_t)b * E_ + (i - W_)];
}

// ---------------------------------------------------------------------------
// Launch
// ---------------------------------------------------------------------------
extern "C" void kernel_launch(void* const* d_in, const int* in_sizes, int n_in,
                              void* d_out, int out_size)
{
    const int*   E_tm1 = (const int*)d_in[0];
    const float* y_tm1 = (const float*)d_in[1];
    const float* h     = (const float*)d_in[2];
    const float* emb   = (const float*)d_in[3];
    const float* W_ih  = (const float*)d_in[4];
    const float* b_ih  = (const float*)d_in[5];
    const float* W_hh  = (const float*)d_in[6];
    const float* b_hh  = (const float*)d_in[7];
    const float* W_out = (const float*)d_in[8];
    const float* b_out = (const float*)d_in[9];
    const float* Wh1 = (const float*)d_in[10]; const float* bh1 = (const float*)d_in[11];
    const float* Wh2 = (const float*)d_in[12]; const float* bh2 = (const float*)d_in[13];
    const float* Wc1 = (const float*)d_in[14]; const float* bc1 = (const float*)d_in[15];
    const float* Wc2 = (const float*)d_in[16]; const float* bc2 = (const float*)d_in[17];
    const float* Wa1 = (const float*)d_in[18]; const float* ba1 = (const float*)d_in[19];
    const float* Wa2 = (const float*)d_in[20]; const float* ba2 = (const float*)d_in[21];
    const float* Wb  = (const float*)d_in[22]; const float* bb  = (const float*)d_in[23];
    float* out = (float*)d_out;

    Scratch* s = nullptr;
    cudaGetSymbolAddress((void**)&s, g_s);

    const int GN_D  = (D_ + 63) / 64;            // 29
    const int GN_4D = (4 * D_ + 127) / 128;      // 57
    const int GN_V  = V_ / 128;                  // 250

    // 1. encoder mean
    havg_kernel<<<dim3(B_, E_ / 256), 256>>>(h, s->havg);

    // 2. init-state layer1 -> partials (KS=2)
    {
        SKJob2 jj;
        jj.j[0] = {s->havg, nullptr, nullptr, nullptr, 0, Wh1, E_, E_, D_, s->skpA[0][0]};
        jj.j[1] = {s->havg, nullptr, nullptr, nullptr, 0, Wc1, E_, E_, D_, s->skpA[1][0]};
        sk_gemm_kernel<64><<<dim3(GN_D, 2, 2), 256>>>(jj);
    }
    // 3. layer2, A = relu(sum L1 partials + b1) fused (KS=3)
    {
        SKJob2 jj;
        jj.j[0] = {s->skpA[0][0], s->skpA[0][1], nullptr, bh1, 1, Wh2, D_, D_, D_, s->skpB[0][0]};
        jj.j[1] = {s->skpA[1][0], s->skpA[1][1], nullptr, bc1, 1, Wc2, D_, D_, D_, s->skpB[1][0]};
        sk_gemm_kernel<64><<<dim3(GN_D, 2, 3), 256>>>(jj);
    }
    // 4. qpart = (h0 = sum L2 partials + bh2) @ Wa1[:, :D]^T  (KS=3)
    {
        SKJob2 jj;
        jj.j[0] = {s->skpB[0][0], s->skpB[0][1], s->skpB[0][2], bh2, 0, Wa1, D_, DE_, D_, s->skpA[0][0]};
        jj.j[1] = jj.j[0];
        sk_gemm_kernel<64><<<dim3(GN_D, 1, 3), 256>>>(jj);
    }
    // 5. qpart reduce (+ ba1)
    sk_reduce3_kernel<<<(B_ * D_ + 255) / 256, 256>>>(s->skpA[0][0], ba1, s->qpart);

    // 6. fused scores GEMM (fp16 HMMA + ldmatrix)
    mma_scores_kernel<<<dim3(S_ / 4, 3), 256>>>(h, Wa1 + D_, s->qpart, Wa2, s->spart);

    // 7. argmax of y_tm1
    argmax_kernel<<<B_, 256>>>(y_tm1, s->amax);

    // 8. softmax + beta (h0 virtual from partials)
    float* aw_out = out + (size_t)B_ * V_ + 2 * (size_t)B_ * D_;
    softmax_beta_kernel<<<B_, 256>>>(s->spart, s->skpB[0][0], s->skpB[0][1], s->skpB[0][2],
                                     bh2, Wb, bb, ba2, aw_out, s->beta);

    // 9. context
    ctx_kernel<<<dim3(B_, E_ / 256), 256>>>(h, aw_out, s->beta, s->ctx);

    // 10. LSTM input + gates (h0 virtual in job1)
    xbuild_kernel<<<dim3(B_, WE_ / 256), 256>>>(emb, E_tm1, s->ctx, s->x);
    {
        SKJob2 jj;
        jj.j[0] = {s->x, nullptr, nullptr, nullptr, 0, W_ih, WE_, WE_, 4 * D_, s->gp0};
        jj.j[1] = {s->skpB[0][0], s->skpB[0][1], s->skpB[0][2], bh2, 0, W_hh, D_, D_, 4 * D_, s->gp1};
        sk_gemm_kernel<128><<<dim3(GN_4D, 2, 1), 256>>>(jj);
    }

    // 11. LSTM pointwise (c0 virtual from partials)
    lstm_kernel<<<dim3(B_, (D_ + 255) / 256), 256>>>(
        s->gp0, s->gp1, b_ih, b_hh,
        s->skpB[1][0], s->skpB[1][1], s->skpB[1][2], bc2, out, s->z);

    // 12. z tail
    zbuild_kernel<<<dim3(B_, WE_ / 256), 256>>>(emb, s->amax, s->ctx, s->z);

    // 13. logits
    logits_kernel<<<GN_V, 256>>>(s->z, W_out, b_out, out);
}